// round 10
// baseline (speedup 1.0000x reference)
#include <cuda_runtime.h>
#include <cuda_fp16.h>

// NonLocalAttention: B=4, C=256, H=W=64 -> N=4096, C8=32, C2=128
//   proj_tc_kernel : theta/phi/g projections (tf32 mma, split-x), fp16 out
//   flash_tc_kernel: fp16 m16n8k16 flash attention, online-max, 3 CTA/SM
//   out_tc_kernel  : w_o @ att + b_o + x (fp16 mma, split-att)

#define B_ 4
#define C_ 256
#define N_ 4096
#define C8_ 32
#define C2_ 128

__device__ __half d_theta[(size_t)B_ * C8_ * N_];   // theta * log2e
__device__ __half d_phi[(size_t)B_ * C8_ * N_];
__device__ __half d_g[(size_t)B_ * C2_ * N_];       // [b][c2][n]
__device__ float  d_att[(size_t)B_ * N_ * C2_];

// ---- intrinsics ----
__device__ __forceinline__ unsigned cvt_tf32(float x) {
    unsigned r;
    asm("cvt.rna.tf32.f32 %0, %1;" : "=r"(r) : "f"(x));
    return r;
}
__device__ __forceinline__ float cvt_tf32f(float x) {
    return __uint_as_float(cvt_tf32(x));
}
__device__ __forceinline__ float ex2f(float x) {
    float r;
    asm("ex2.approx.f32 %0, %1;" : "=f"(r) : "f"(x));
    return r;
}
__device__ __forceinline__ void mma_tf32(
    float& c0, float& c1, float& c2, float& c3,
    unsigned a0, unsigned a1, unsigned a2, unsigned a3,
    unsigned b0, unsigned b1) {
    asm("mma.sync.aligned.m16n8k8.row.col.f32.tf32.tf32.f32 "
        "{%0,%1,%2,%3}, {%4,%5,%6,%7}, {%8,%9}, {%0,%1,%2,%3};"
        : "+f"(c0), "+f"(c1), "+f"(c2), "+f"(c3)
        : "r"(a0), "r"(a1), "r"(a2), "r"(a3), "r"(b0), "r"(b1));
}
__device__ __forceinline__ void mma_f16(
    float& c0, float& c1, float& c2, float& c3,
    unsigned a0, unsigned a1, unsigned a2, unsigned a3,
    unsigned b0, unsigned b1) {
    asm("mma.sync.aligned.m16n8k16.row.col.f32.f16.f16.f32 "
        "{%0,%1,%2,%3}, {%4,%5,%6,%7}, {%8,%9}, {%0,%1,%2,%3};"
        : "+f"(c0), "+f"(c1), "+f"(c2), "+f"(c3)
        : "r"(a0), "r"(a1), "r"(a2), "r"(a3), "r"(b0), "r"(b1));
}
__device__ __forceinline__ unsigned packh2(float lo, float hi) {
    __half2 h = __floats2half2_rn(lo, hi);
    return *(unsigned*)&h;
}

// ============================================================================
// Kernel 1: projections via tf32 mma, split-x. fp16 outputs. (unchanged R9)
// ============================================================================
__global__ void __launch_bounds__(256) proj_tc_kernel(
    const float* __restrict__ x,
    const float* __restrict__ wt, const float* __restrict__ bt,
    const float* __restrict__ wp, const float* __restrict__ bp,
    const float* __restrict__ wg, const float* __restrict__ bg) {
    extern __shared__ float sm[];
    float* ws = sm;                 // [32][36]
    float* xh = sm + 32 * 36;       // [32][136]
    float* xl = xh + 32 * 136;      // [32][136]

    const int b  = blockIdx.y;
    const int Mbase = (blockIdx.x >> 5) * 32;
    const int N0    = (blockIdx.x & 31) * 128;
    const int tid  = threadIdx.x;
    const int wid  = tid >> 5, lane = tid & 31;
    const int m0   = (wid >> 2) * 16;
    const int n0w  = (wid & 3) * 32;
    const int qr = lane >> 2, qc = lane & 3;

    float acc[4][4];
#pragma unroll
    for (int nt = 0; nt < 4; nt++)
#pragma unroll
        for (int j = 0; j < 4; j++) acc[nt][j] = 0.f;

    for (int kp = 0; kp < 8; kp++) {
        const int k0 = kp * 32;
        __syncthreads();
#pragma unroll
        for (int i = 0; i < 4; i++) {
            int idx = i * 256 + tid;
            int r = idx >> 5, kk = idx & 31;
            int o = Mbase + r;
            const float* src = (o < 32) ? wt + o * C_
                             : (o < 64) ? wp + (o - 32) * C_
                                        : wg + (o - 64) * C_;
            ws[r * 36 + kk] = cvt_tf32f(src[k0 + kk]);
        }
#pragma unroll
        for (int i = 0; i < 4; i++) {
            int idx = i * 256 + tid;
            int cc = idx >> 5, nn4 = idx & 31;
            float4 v = *(const float4*)(
                x + ((size_t)(b * C_ + k0 + cc)) * N_ + N0 + nn4 * 4);
            float4 h, l;
            h.x = cvt_tf32f(v.x); l.x = v.x - h.x;
            h.y = cvt_tf32f(v.y); l.y = v.y - h.y;
            h.z = cvt_tf32f(v.z); l.z = v.z - h.z;
            h.w = cvt_tf32f(v.w); l.w = v.w - h.w;
            *(float4*)(xh + cc * 136 + nn4 * 4) = h;
            *(float4*)(xl + cc * 136 + nn4 * 4) = l;
        }
        __syncthreads();

#pragma unroll
        for (int ks = 0; ks < 4; ks++) {
            const float* wrow = ws + (m0 + qr) * 36 + ks * 8 + qc;
            unsigned a0 = __float_as_uint(wrow[0]);
            unsigned a1 = __float_as_uint(wrow[8 * 36]);
            unsigned a2 = __float_as_uint(wrow[4]);
            unsigned a3 = __float_as_uint(wrow[8 * 36 + 4]);
            const float* bh = xh + (ks * 8 + qc) * 136 + n0w + qr;
            const float* bl = xl + (ks * 8 + qc) * 136 + n0w + qr;
#pragma unroll
            for (int nt = 0; nt < 4; nt++) {
                unsigned b0 = __float_as_uint(bh[nt * 8]);
                unsigned b1 = __float_as_uint(bh[4 * 136 + nt * 8]);
                mma_tf32(acc[nt][0], acc[nt][1], acc[nt][2], acc[nt][3],
                         a0, a1, a2, a3, b0, b1);
                unsigned l0 = __float_as_uint(bl[nt * 8]);
                unsigned l1 = __float_as_uint(bl[4 * 136 + nt * 8]);
                mma_tf32(acc[nt][0], acc[nt][1], acc[nt][2], acc[nt][3],
                         a0, a1, a2, a3, l0, l1);
            }
        }
    }

    const float LOG2E = 1.4426950408889634f;
#pragma unroll
    for (int rr = 0; rr < 2; rr++) {
        int o = Mbase + m0 + qr + rr * 8;
        if (o < 32) {
            float bias = bt[o];
            __half2* dst = (__half2*)(d_theta + ((size_t)b * C8_ + o) * N_ +
                                      N0 + n0w + qc * 2);
#pragma unroll
            for (int nt = 0; nt < 4; nt++)
                dst[nt * 4] = __floats2half2_rn(
                    (acc[nt][rr * 2] + bias) * LOG2E,
                    (acc[nt][rr * 2 + 1] + bias) * LOG2E);
        } else if (o < 64) {
            float bias = bp[o - 32];
            __half2* dst = (__half2*)(d_phi + ((size_t)b * C8_ + (o - 32)) * N_ +
                                      N0 + n0w + qc * 2);
#pragma unroll
            for (int nt = 0; nt < 4; nt++)
                dst[nt * 4] = __floats2half2_rn(
                    acc[nt][rr * 2] + bias, acc[nt][rr * 2 + 1] + bias);
        } else {
            float bias = bg[o - 64];
            __half2* dst = (__half2*)(d_g + ((size_t)b * C2_ + (o - 64)) * N_ +
                                      N0 + n0w + qc * 2);
#pragma unroll
            for (int nt = 0; nt < 4; nt++)
                dst[nt * 4] = __floats2half2_rn(
                    acc[nt][rr * 2] + bias, acc[nt][rr * 2 + 1] + bias);
        }
    }
}

// ============================================================================
// Kernel 2: fp16 flash attention (R9) with 3-CTA/SM reg budget.
// ============================================================================
#define PHI_STR 40
#define G_STR   72

__global__ void __launch_bounds__(128, 3) flash_tc_kernel() {
    extern __shared__ __half smh[];
    __half* phi_s = smh;                     // 64*40 halves
    __half* g_s   = smh + 64 * PHI_STR;      // 128*72 halves

    const int b   = blockIdx.y;
    const int q0  = blockIdx.x * 64;
    const int tid = threadIdx.x;
    const int w    = tid >> 5;
    const int lane = tid & 31;
    const int qr = lane >> 2;
    const int qc = lane & 3;
    const int row0 = q0 + w * 16 + qr;

    unsigned at[2][4];
    {
        const __half* tp = d_theta + (size_t)b * C8_ * N_;
#pragma unroll
        for (int ks = 0; ks < 2; ks++) {
            int c = ks * 16 + 2 * qc;
            at[ks][0] = packh2(__half2float(tp[(size_t)c * N_ + row0]),
                               __half2float(tp[(size_t)(c + 1) * N_ + row0]));
            at[ks][1] = packh2(__half2float(tp[(size_t)c * N_ + row0 + 8]),
                               __half2float(tp[(size_t)(c + 1) * N_ + row0 + 8]));
            at[ks][2] = packh2(__half2float(tp[(size_t)(c + 8) * N_ + row0]),
                               __half2float(tp[(size_t)(c + 9) * N_ + row0]));
            at[ks][3] = packh2(__half2float(tp[(size_t)(c + 8) * N_ + row0 + 8]),
                               __half2float(tp[(size_t)(c + 9) * N_ + row0 + 8]));
        }
    }

    float O[16][4];
#pragma unroll
    for (int nt = 0; nt < 16; nt++)
#pragma unroll
        for (int j = 0; j < 4; j++) O[nt][j] = 0.f;
    float m0 = -1e30f, m1 = -1e30f, l0 = 0.f, l1 = 0.f;

    for (int kt = 0; kt < N_; kt += 64) {
        __syncthreads();
#pragma unroll
        for (int i = 0; i < 8; i++) {
            int idx = i * 128 + tid;
            int c = idx >> 5, kc = idx & 31;
            __half2 v = *(const __half2*)(
                d_phi + ((size_t)b * C8_ + c) * N_ + kt + kc * 2);
            phi_s[(kc * 2) * PHI_STR + c]     = __low2half(v);
            phi_s[(kc * 2 + 1) * PHI_STR + c] = __high2half(v);
        }
#pragma unroll
        for (int i = 0; i < 16; i++) {
            int idx = i * 128 + tid;
            int c2 = idx >> 4, kq = idx & 15;
            uint2 v = *(const uint2*)(
                d_g + ((size_t)b * C2_ + c2) * N_ + kt + kq * 4);
            *(uint2*)(g_s + c2 * G_STR + kq * 4) = v;
        }
        __syncthreads();

        float s[8][4];
#pragma unroll
        for (int nt = 0; nt < 8; nt++)
#pragma unroll
            for (int j = 0; j < 4; j++) s[nt][j] = 0.f;

#pragma unroll
        for (int ks = 0; ks < 2; ks++) {
#pragma unroll
            for (int nt = 0; nt < 8; nt++) {
                const __half* pb = phi_s + (nt * 8 + qr) * PHI_STR + ks * 16 + 2 * qc;
                unsigned b0 = *(const unsigned*)pb;
                unsigned b1 = *(const unsigned*)(pb + 8);
                mma_f16(s[nt][0], s[nt][1], s[nt][2], s[nt][3],
                        at[ks][0], at[ks][1], at[ks][2], at[ks][3], b0, b1);
            }
        }

        float rm0 = -1e30f, rm1 = -1e30f;
#pragma unroll
        for (int nt = 0; nt < 8; nt++) {
            rm0 = fmaxf(rm0, fmaxf(s[nt][0], s[nt][1]));
            rm1 = fmaxf(rm1, fmaxf(s[nt][2], s[nt][3]));
        }
        rm0 = fmaxf(rm0, __shfl_xor_sync(0xffffffffu, rm0, 1, 4));
        rm0 = fmaxf(rm0, __shfl_xor_sync(0xffffffffu, rm0, 2, 4));
        rm1 = fmaxf(rm1, __shfl_xor_sync(0xffffffffu, rm1, 1, 4));
        rm1 = fmaxf(rm1, __shfl_xor_sync(0xffffffffu, rm1, 2, 4));
        float mn0 = fmaxf(m0, rm0), mn1 = fmaxf(m1, rm1);
        float cr0 = ex2f(m0 - mn0), cr1 = ex2f(m1 - mn1);
        m0 = mn0; m1 = mn1;
#pragma unroll
        for (int nt = 0; nt < 16; nt++) {
            O[nt][0] *= cr0; O[nt][1] *= cr0;
            O[nt][2] *= cr1; O[nt][3] *= cr1;
        }

        unsigned pk[8][2];
        float rs0 = 0.f, rs1 = 0.f;
#pragma unroll
        for (int nt = 0; nt < 8; nt++) {
            float e0 = ex2f(s[nt][0] - mn0);
            float e1 = ex2f(s[nt][1] - mn0);
            float e2 = ex2f(s[nt][2] - mn1);
            float e3 = ex2f(s[nt][3] - mn1);
            rs0 += e0 + e1; rs1 += e2 + e3;
            pk[nt][0] = packh2(e0, e1);
            pk[nt][1] = packh2(e2, e3);
        }
        l0 = l0 * cr0 + rs0;
        l1 = l1 * cr1 + rs1;

#pragma unroll
        for (int kb = 0; kb < 4; kb++) {
            unsigned a0 = pk[2 * kb][0];
            unsigned a1 = pk[2 * kb][1];
            unsigned a2 = pk[2 * kb + 1][0];
            unsigned a3 = pk[2 * kb + 1][1];
#pragma unroll
            for (int nt = 0; nt < 16; nt++) {
                const __half* gb = g_s + (nt * 8 + qr) * G_STR + kb * 16 + 2 * qc;
                unsigned b0 = *(const unsigned*)gb;
                unsigned b1 = *(const unsigned*)(gb + 8);
                mma_f16(O[nt][0], O[nt][1], O[nt][2], O[nt][3],
                        a0, a1, a2, a3, b0, b1);
            }
        }
    }

    l0 += __shfl_xor_sync(0xffffffffu, l0, 1, 4);
    l0 += __shfl_xor_sync(0xffffffffu, l0, 2, 4);
    l1 += __shfl_xor_sync(0xffffffffu, l1, 1, 4);
    l1 += __shfl_xor_sync(0xffffffffu, l1, 2, 4);
    float inv0 = 1.0f / l0;
    float inv1 = 1.0f / l1;

    float* dst0 = d_att + ((size_t)b * N_ + row0) * C2_ + qc * 2;
#pragma unroll
    for (int nt = 0; nt < 16; nt++) {
        *(float2*)(dst0 + nt * 8) =
            make_float2(O[nt][0] * inv0, O[nt][1] * inv0);
        *(float2*)(dst0 + 8 * C2_ + nt * 8) =
            make_float2(O[nt][2] * inv1, O[nt][3] * inv1);
    }
}

// ============================================================================
// Kernel 3: out = w_o @ att + b_o + x via fp16 mma, split-att.
// A = wo[c][c2] fp16 (stride 136 halves); B = att[n][c2] hi/lo fp16
// (stride 40 halves). No transpose needed anywhere.
// ============================================================================
#define WO_STR 136
#define AT_STR 40

__global__ void __launch_bounds__(256) out_tc_kernel(
    const float* __restrict__ wo, const float* __restrict__ bo,
    const float* __restrict__ x, float* __restrict__ out) {
    extern __shared__ __half smh[];
    __half* w_s = smh;                       // [32][WO_STR]
    __half* ah  = smh + 32 * WO_STR;         // [128][AT_STR]
    __half* al  = ah + 128 * AT_STR;         // [128][AT_STR]

    const int b  = blockIdx.y;
    const int Cbase = (blockIdx.x >> 5) * 32;
    const int N0    = (blockIdx.x & 31) * 128;
    const int tid  = threadIdx.x;
    const int wid  = tid >> 5, lane = tid & 31;
    const int m0   = (wid >> 2) * 16;
    const int n0w  = (wid & 3) * 32;
    const int qr = lane >> 2, qc = lane & 3;

    // stage wo [32 c][128 c2] fp16 once
#pragma unroll
    for (int i = 0; i < 16; i++) {
        int idx = i * 256 + tid;
        int r = idx >> 7, kk = idx & 127;
        w_s[r * WO_STR + kk] = __float2half_rn(wo[(Cbase + r) * C2_ + kk]);
    }

    float acc[4][4];
#pragma unroll
    for (int nt = 0; nt < 4; nt++)
#pragma unroll
        for (int j = 0; j < 4; j++) acc[nt][j] = 0.f;

    for (int kp = 0; kp < 4; kp++) {
        const int k0 = kp * 32;
        __syncthreads();
        // stage att [128 n][32 k] hi/lo fp16
#pragma unroll
        for (int i = 0; i < 4; i++) {
            int idx = i * 256 + tid;
            int nn = idx >> 3, kk4 = idx & 7;
            float4 v = *(const float4*)(
                d_att + ((size_t)b * N_ + N0 + nn) * C2_ + k0 + kk4 * 4);
            __half2 h01 = __floats2half2_rn(v.x, v.y);
            __half2 h23 = __floats2half2_rn(v.z, v.w);
            __half2 l01 = __floats2half2_rn(v.x - __half2float(__low2half(h01)),
                                            v.y - __half2float(__high2half(h01)));
            __half2 l23 = __floats2half2_rn(v.z - __half2float(__low2half(h23)),
                                            v.w - __half2float(__high2half(h23)));
            *(__half2*)(ah + nn * AT_STR + kk4 * 4)     = h01;
            *(__half2*)(ah + nn * AT_STR + kk4 * 4 + 2) = h23;
            *(__half2*)(al + nn * AT_STR + kk4 * 4)     = l01;
            *(__half2*)(al + nn * AT_STR + kk4 * 4 + 2) = l23;
        }
        __syncthreads();

#pragma unroll
        for (int ks = 0; ks < 2; ks++) {
            const __half* wrow = w_s + (m0 + qr) * WO_STR + k0 + ks * 16 + 2 * qc;
            unsigned a0 = *(const unsigned*)wrow;
            unsigned a1 = *(const unsigned*)(wrow + 8 * WO_STR);
            unsigned a2 = *(const unsigned*)(wrow + 8);
            unsigned a3 = *(const unsigned*)(wrow + 8 * WO_STR + 8);
#pragma unroll
            for (int nt = 0; nt < 4; nt++) {
                const __half* bh = ah + (n0w + nt * 8 + qr) * AT_STR + ks * 16 + 2 * qc;
                const __half* bl = al + (n0w + nt * 8 + qr) * AT_STR + ks * 16 + 2 * qc;
                unsigned b0 = *(const unsigned*)bh;
                unsigned b1 = *(const unsigned*)(bh + 8);
                mma_f16(acc[nt][0], acc[nt][1], acc[nt][2], acc[nt][3],
                        a0, a1, a2, a3, b0, b1);
                unsigned c0 = *(const unsigned*)bl;
                unsigned c1 = *(const unsigned*)(bl + 8);
                mma_f16(acc[nt][0], acc[nt][1], acc[nt][2], acc[nt][3],
                        a0, a1, a2, a3, c0, c1);
            }
        }
    }

#pragma unroll
    for (int rr = 0; rr < 2; rr++) {
        int c = Cbase + m0 + qr + rr * 8;
        float bias = bo[c];
#pragma unroll
        for (int nt = 0; nt < 4; nt++) {
            int n = N0 + n0w + qc * 2 + nt * 8;
            size_t idx = ((size_t)b * C_ + c) * N_ + n;
            float2 xv = *(const float2*)(x + idx);
            *(float2*)(out + idx) = make_float2(
                acc[nt][rr * 2] + bias + xv.x,
                acc[nt][rr * 2 + 1] + bias + xv.y);
        }
    }
}

// ============================================================================
extern "C" void kernel_launch(void* const* d_in, const int* in_sizes, int n_in,
                              void* d_out, int out_size) {
    (void)in_sizes; (void)n_in; (void)out_size;
    const float* x  = (const float*)d_in[0];
    const float* wt = (const float*)d_in[1];
    const float* bt = (const float*)d_in[2];
    const float* wp = (const float*)d_in[3];
    const float* bp = (const float*)d_in[4];
    const float* wg = (const float*)d_in[5];
    const float* bg = (const float*)d_in[6];
    const float* wo = (const float*)d_in[7];
    const float* bo = (const float*)d_in[8];
    float* out = (float*)d_out;

    const int smem_proj  = (32 * 36 + 2 * 32 * 136) * 4;         // 39424
    const int smem_flash = (64 * PHI_STR + 128 * G_STR) * 2;     // 23552
    const int smem_out   = (32 * WO_STR + 2 * 128 * AT_STR) * 2; // 29184

    cudaFuncSetAttribute(proj_tc_kernel,
                         cudaFuncAttributeMaxDynamicSharedMemorySize, smem_proj);
    cudaFuncSetAttribute(flash_tc_kernel,
                         cudaFuncAttributeMaxDynamicSharedMemorySize, smem_flash);
    cudaFuncSetAttribute(out_tc_kernel,
                         cudaFuncAttributeMaxDynamicSharedMemorySize, smem_out);

    proj_tc_kernel<<<dim3(192, B_), 256, smem_proj>>>(x, wt, bt, wp, bp, wg, bg);
    flash_tc_kernel<<<dim3(N_ / 64, B_), 128, smem_flash>>>();
    out_tc_kernel<<<dim3(256, B_), 256, smem_out>>>(wo, bo, x, out);
}

// round 11
// speedup vs baseline: 1.0929x; 1.0929x over previous
#include <cuda_runtime.h>
#include <cuda_fp16.h>

// NonLocalAttention: B=4, C=256, H=W=64 -> N=4096, C8=32, C2=128
//   proj_tc_kernel : theta/phi/g projections (tf32 mma, split-x), fp16 out
//   flash_tc_kernel: fp16 m16n8k16 flash attention (exact R9: lb(128,2))
//   out_tc_kernel  : w_o @ att + b_o + x (fp16 mma, split-att)

#define B_ 4
#define C_ 256
#define N_ 4096
#define C8_ 32
#define C2_ 128

__device__ __half d_theta[(size_t)B_ * C8_ * N_];   // theta * log2e
__device__ __half d_phi[(size_t)B_ * C8_ * N_];
__device__ __half d_g[(size_t)B_ * C2_ * N_];       // [b][c2][n]
__device__ float  d_att[(size_t)B_ * N_ * C2_];

// ---- intrinsics ----
__device__ __forceinline__ unsigned cvt_tf32(float x) {
    unsigned r;
    asm("cvt.rna.tf32.f32 %0, %1;" : "=r"(r) : "f"(x));
    return r;
}
__device__ __forceinline__ float cvt_tf32f(float x) {
    return __uint_as_float(cvt_tf32(x));
}
__device__ __forceinline__ float ex2f(float x) {
    float r;
    asm("ex2.approx.f32 %0, %1;" : "=f"(r) : "f"(x));
    return r;
}
__device__ __forceinline__ void mma_tf32(
    float& c0, float& c1, float& c2, float& c3,
    unsigned a0, unsigned a1, unsigned a2, unsigned a3,
    unsigned b0, unsigned b1) {
    asm("mma.sync.aligned.m16n8k8.row.col.f32.tf32.tf32.f32 "
        "{%0,%1,%2,%3}, {%4,%5,%6,%7}, {%8,%9}, {%0,%1,%2,%3};"
        : "+f"(c0), "+f"(c1), "+f"(c2), "+f"(c3)
        : "r"(a0), "r"(a1), "r"(a2), "r"(a3), "r"(b0), "r"(b1));
}
__device__ __forceinline__ void mma_f16(
    float& c0, float& c1, float& c2, float& c3,
    unsigned a0, unsigned a1, unsigned a2, unsigned a3,
    unsigned b0, unsigned b1) {
    asm("mma.sync.aligned.m16n8k16.row.col.f32.f16.f16.f32 "
        "{%0,%1,%2,%3}, {%4,%5,%6,%7}, {%8,%9}, {%0,%1,%2,%3};"
        : "+f"(c0), "+f"(c1), "+f"(c2), "+f"(c3)
        : "r"(a0), "r"(a1), "r"(a2), "r"(a3), "r"(b0), "r"(b1));
}
__device__ __forceinline__ unsigned packh2(float lo, float hi) {
    __half2 h = __floats2half2_rn(lo, hi);
    return *(unsigned*)&h;
}

// ============================================================================
// Kernel 1: projections via tf32 mma, split-x. fp16 outputs. (unchanged R9)
// ============================================================================
__global__ void __launch_bounds__(256) proj_tc_kernel(
    const float* __restrict__ x,
    const float* __restrict__ wt, const float* __restrict__ bt,
    const float* __restrict__ wp, const float* __restrict__ bp,
    const float* __restrict__ wg, const float* __restrict__ bg) {
    extern __shared__ float sm[];
    float* ws = sm;                 // [32][36]
    float* xh = sm + 32 * 36;       // [32][136]
    float* xl = xh + 32 * 136;      // [32][136]

    const int b  = blockIdx.y;
    const int Mbase = (blockIdx.x >> 5) * 32;
    const int N0    = (blockIdx.x & 31) * 128;
    const int tid  = threadIdx.x;
    const int wid  = tid >> 5, lane = tid & 31;
    const int m0   = (wid >> 2) * 16;
    const int n0w  = (wid & 3) * 32;
    const int qr = lane >> 2, qc = lane & 3;

    float acc[4][4];
#pragma unroll
    for (int nt = 0; nt < 4; nt++)
#pragma unroll
        for (int j = 0; j < 4; j++) acc[nt][j] = 0.f;

    for (int kp = 0; kp < 8; kp++) {
        const int k0 = kp * 32;
        __syncthreads();
#pragma unroll
        for (int i = 0; i < 4; i++) {
            int idx = i * 256 + tid;
            int r = idx >> 5, kk = idx & 31;
            int o = Mbase + r;
            const float* src = (o < 32) ? wt + o * C_
                             : (o < 64) ? wp + (o - 32) * C_
                                        : wg + (o - 64) * C_;
            ws[r * 36 + kk] = cvt_tf32f(src[k0 + kk]);
        }
#pragma unroll
        for (int i = 0; i < 4; i++) {
            int idx = i * 256 + tid;
            int cc = idx >> 5, nn4 = idx & 31;
            float4 v = *(const float4*)(
                x + ((size_t)(b * C_ + k0 + cc)) * N_ + N0 + nn4 * 4);
            float4 h, l;
            h.x = cvt_tf32f(v.x); l.x = v.x - h.x;
            h.y = cvt_tf32f(v.y); l.y = v.y - h.y;
            h.z = cvt_tf32f(v.z); l.z = v.z - h.z;
            h.w = cvt_tf32f(v.w); l.w = v.w - h.w;
            *(float4*)(xh + cc * 136 + nn4 * 4) = h;
            *(float4*)(xl + cc * 136 + nn4 * 4) = l;
        }
        __syncthreads();

#pragma unroll
        for (int ks = 0; ks < 4; ks++) {
            const float* wrow = ws + (m0 + qr) * 36 + ks * 8 + qc;
            unsigned a0 = __float_as_uint(wrow[0]);
            unsigned a1 = __float_as_uint(wrow[8 * 36]);
            unsigned a2 = __float_as_uint(wrow[4]);
            unsigned a3 = __float_as_uint(wrow[8 * 36 + 4]);
            const float* bh = xh + (ks * 8 + qc) * 136 + n0w + qr;
            const float* bl = xl + (ks * 8 + qc) * 136 + n0w + qr;
#pragma unroll
            for (int nt = 0; nt < 4; nt++) {
                unsigned b0 = __float_as_uint(bh[nt * 8]);
                unsigned b1 = __float_as_uint(bh[4 * 136 + nt * 8]);
                mma_tf32(acc[nt][0], acc[nt][1], acc[nt][2], acc[nt][3],
                         a0, a1, a2, a3, b0, b1);
                unsigned l0 = __float_as_uint(bl[nt * 8]);
                unsigned l1 = __float_as_uint(bl[4 * 136 + nt * 8]);
                mma_tf32(acc[nt][0], acc[nt][1], acc[nt][2], acc[nt][3],
                         a0, a1, a2, a3, l0, l1);
            }
        }
    }

    const float LOG2E = 1.4426950408889634f;
#pragma unroll
    for (int rr = 0; rr < 2; rr++) {
        int o = Mbase + m0 + qr + rr * 8;
        if (o < 32) {
            float bias = bt[o];
            __half2* dst = (__half2*)(d_theta + ((size_t)b * C8_ + o) * N_ +
                                      N0 + n0w + qc * 2);
#pragma unroll
            for (int nt = 0; nt < 4; nt++)
                dst[nt * 4] = __floats2half2_rn(
                    (acc[nt][rr * 2] + bias) * LOG2E,
                    (acc[nt][rr * 2 + 1] + bias) * LOG2E);
        } else if (o < 64) {
            float bias = bp[o - 32];
            __half2* dst = (__half2*)(d_phi + ((size_t)b * C8_ + (o - 32)) * N_ +
                                      N0 + n0w + qc * 2);
#pragma unroll
            for (int nt = 0; nt < 4; nt++)
                dst[nt * 4] = __floats2half2_rn(
                    acc[nt][rr * 2] + bias, acc[nt][rr * 2 + 1] + bias);
        } else {
            float bias = bg[o - 64];
            __half2* dst = (__half2*)(d_g + ((size_t)b * C2_ + (o - 64)) * N_ +
                                      N0 + n0w + qc * 2);
#pragma unroll
            for (int nt = 0; nt < 4; nt++)
                dst[nt * 4] = __floats2half2_rn(
                    acc[nt][rr * 2] + bias, acc[nt][rr * 2 + 1] + bias);
        }
    }
}

// ============================================================================
// Kernel 2: fp16 flash attention — EXACT R9 (lb(128,2), no tighter cap).
// ============================================================================
#define PHI_STR 40
#define G_STR   72

__global__ void __launch_bounds__(128, 2) flash_tc_kernel() {
    extern __shared__ __half smh[];
    __half* phi_s = smh;                     // 64*40 halves
    __half* g_s   = smh + 64 * PHI_STR;      // 128*72 halves

    const int b   = blockIdx.y;
    const int q0  = blockIdx.x * 64;
    const int tid = threadIdx.x;
    const int w    = tid >> 5;
    const int lane = tid & 31;
    const int qr = lane >> 2;
    const int qc = lane & 3;
    const int row0 = q0 + w * 16 + qr;

    unsigned at[2][4];
    {
        const __half* tp = d_theta + (size_t)b * C8_ * N_;
#pragma unroll
        for (int ks = 0; ks < 2; ks++) {
            int c = ks * 16 + 2 * qc;
            at[ks][0] = packh2(__half2float(tp[(size_t)c * N_ + row0]),
                               __half2float(tp[(size_t)(c + 1) * N_ + row0]));
            at[ks][1] = packh2(__half2float(tp[(size_t)c * N_ + row0 + 8]),
                               __half2float(tp[(size_t)(c + 1) * N_ + row0 + 8]));
            at[ks][2] = packh2(__half2float(tp[(size_t)(c + 8) * N_ + row0]),
                               __half2float(tp[(size_t)(c + 9) * N_ + row0]));
            at[ks][3] = packh2(__half2float(tp[(size_t)(c + 8) * N_ + row0 + 8]),
                               __half2float(tp[(size_t)(c + 9) * N_ + row0 + 8]));
        }
    }

    float O[16][4];
#pragma unroll
    for (int nt = 0; nt < 16; nt++)
#pragma unroll
        for (int j = 0; j < 4; j++) O[nt][j] = 0.f;
    float m0 = -1e30f, m1 = -1e30f, l0 = 0.f, l1 = 0.f;

    for (int kt = 0; kt < N_; kt += 64) {
        __syncthreads();
#pragma unroll
        for (int i = 0; i < 8; i++) {
            int idx = i * 128 + tid;
            int c = idx >> 5, kc = idx & 31;
            __half2 v = *(const __half2*)(
                d_phi + ((size_t)b * C8_ + c) * N_ + kt + kc * 2);
            phi_s[(kc * 2) * PHI_STR + c]     = __low2half(v);
            phi_s[(kc * 2 + 1) * PHI_STR + c] = __high2half(v);
        }
#pragma unroll
        for (int i = 0; i < 16; i++) {
            int idx = i * 128 + tid;
            int c2 = idx >> 4, kq = idx & 15;
            uint2 v = *(const uint2*)(
                d_g + ((size_t)b * C2_ + c2) * N_ + kt + kq * 4);
            *(uint2*)(g_s + c2 * G_STR + kq * 4) = v;
        }
        __syncthreads();

        float s[8][4];
#pragma unroll
        for (int nt = 0; nt < 8; nt++)
#pragma unroll
            for (int j = 0; j < 4; j++) s[nt][j] = 0.f;

#pragma unroll
        for (int ks = 0; ks < 2; ks++) {
#pragma unroll
            for (int nt = 0; nt < 8; nt++) {
                const __half* pb = phi_s + (nt * 8 + qr) * PHI_STR + ks * 16 + 2 * qc;
                unsigned b0 = *(const unsigned*)pb;
                unsigned b1 = *(const unsigned*)(pb + 8);
                mma_f16(s[nt][0], s[nt][1], s[nt][2], s[nt][3],
                        at[ks][0], at[ks][1], at[ks][2], at[ks][3], b0, b1);
            }
        }

        float rm0 = -1e30f, rm1 = -1e30f;
#pragma unroll
        for (int nt = 0; nt < 8; nt++) {
            rm0 = fmaxf(rm0, fmaxf(s[nt][0], s[nt][1]));
            rm1 = fmaxf(rm1, fmaxf(s[nt][2], s[nt][3]));
        }
        rm0 = fmaxf(rm0, __shfl_xor_sync(0xffffffffu, rm0, 1, 4));
        rm0 = fmaxf(rm0, __shfl_xor_sync(0xffffffffu, rm0, 2, 4));
        rm1 = fmaxf(rm1, __shfl_xor_sync(0xffffffffu, rm1, 1, 4));
        rm1 = fmaxf(rm1, __shfl_xor_sync(0xffffffffu, rm1, 2, 4));
        float mn0 = fmaxf(m0, rm0), mn1 = fmaxf(m1, rm1);
        float cr0 = ex2f(m0 - mn0), cr1 = ex2f(m1 - mn1);
        m0 = mn0; m1 = mn1;
#pragma unroll
        for (int nt = 0; nt < 16; nt++) {
            O[nt][0] *= cr0; O[nt][1] *= cr0;
            O[nt][2] *= cr1; O[nt][3] *= cr1;
        }

        unsigned pk[8][2];
        float rs0 = 0.f, rs1 = 0.f;
#pragma unroll
        for (int nt = 0; nt < 8; nt++) {
            float e0 = ex2f(s[nt][0] - mn0);
            float e1 = ex2f(s[nt][1] - mn0);
            float e2 = ex2f(s[nt][2] - mn1);
            float e3 = ex2f(s[nt][3] - mn1);
            rs0 += e0 + e1; rs1 += e2 + e3;
            pk[nt][0] = packh2(e0, e1);
            pk[nt][1] = packh2(e2, e3);
        }
        l0 = l0 * cr0 + rs0;
        l1 = l1 * cr1 + rs1;

#pragma unroll
        for (int kb = 0; kb < 4; kb++) {
            unsigned a0 = pk[2 * kb][0];
            unsigned a1 = pk[2 * kb][1];
            unsigned a2 = pk[2 * kb + 1][0];
            unsigned a3 = pk[2 * kb + 1][1];
#pragma unroll
            for (int nt = 0; nt < 16; nt++) {
                const __half* gb = g_s + (nt * 8 + qr) * G_STR + kb * 16 + 2 * qc;
                unsigned b0 = *(const unsigned*)gb;
                unsigned b1 = *(const unsigned*)(gb + 8);
                mma_f16(O[nt][0], O[nt][1], O[nt][2], O[nt][3],
                        a0, a1, a2, a3, b0, b1);
            }
        }
    }

    l0 += __shfl_xor_sync(0xffffffffu, l0, 1, 4);
    l0 += __shfl_xor_sync(0xffffffffu, l0, 2, 4);
    l1 += __shfl_xor_sync(0xffffffffu, l1, 1, 4);
    l1 += __shfl_xor_sync(0xffffffffu, l1, 2, 4);
    float inv0 = 1.0f / l0;
    float inv1 = 1.0f / l1;

    float* dst0 = d_att + ((size_t)b * N_ + row0) * C2_ + qc * 2;
#pragma unroll
    for (int nt = 0; nt < 16; nt++) {
        *(float2*)(dst0 + nt * 8) =
            make_float2(O[nt][0] * inv0, O[nt][1] * inv0);
        *(float2*)(dst0 + 8 * C2_ + nt * 8) =
            make_float2(O[nt][2] * inv1, O[nt][3] * inv1);
    }
}

// ============================================================================
// Kernel 3: out = w_o @ att + b_o + x via fp16 mma, split-att. (R10 version)
// ============================================================================
#define WO_STR 136
#define AT_STR 40

__global__ void __launch_bounds__(256) out_tc_kernel(
    const float* __restrict__ wo, const float* __restrict__ bo,
    const float* __restrict__ x, float* __restrict__ out) {
    extern __shared__ __half smh[];
    __half* w_s = smh;                       // [32][WO_STR]
    __half* ah  = smh + 32 * WO_STR;         // [128][AT_STR]
    __half* al  = ah + 128 * AT_STR;         // [128][AT_STR]

    const int b  = blockIdx.y;
    const int Cbase = (blockIdx.x >> 5) * 32;
    const int N0    = (blockIdx.x & 31) * 128;
    const int tid  = threadIdx.x;
    const int wid  = tid >> 5, lane = tid & 31;
    const int m0   = (wid >> 2) * 16;
    const int n0w  = (wid & 3) * 32;
    const int qr = lane >> 2, qc = lane & 3;

#pragma unroll
    for (int i = 0; i < 16; i++) {
        int idx = i * 256 + tid;
        int r = idx >> 7, kk = idx & 127;
        w_s[r * WO_STR + kk] = __float2half_rn(wo[(Cbase + r) * C2_ + kk]);
    }

    float acc[4][4];
#pragma unroll
    for (int nt = 0; nt < 4; nt++)
#pragma unroll
        for (int j = 0; j < 4; j++) acc[nt][j] = 0.f;

    for (int kp = 0; kp < 4; kp++) {
        const int k0 = kp * 32;
        __syncthreads();
#pragma unroll
        for (int i = 0; i < 4; i++) {
            int idx = i * 256 + tid;
            int nn = idx >> 3, kk4 = idx & 7;
            float4 v = *(const float4*)(
                d_att + ((size_t)b * N_ + N0 + nn) * C2_ + k0 + kk4 * 4);
            __half2 h01 = __floats2half2_rn(v.x, v.y);
            __half2 h23 = __floats2half2_rn(v.z, v.w);
            __half2 l01 = __floats2half2_rn(v.x - __half2float(__low2half(h01)),
                                            v.y - __half2float(__high2half(h01)));
            __half2 l23 = __floats2half2_rn(v.z - __half2float(__low2half(h23)),
                                            v.w - __half2float(__high2half(h23)));
            *(__half2*)(ah + nn * AT_STR + kk4 * 4)     = h01;
            *(__half2*)(ah + nn * AT_STR + kk4 * 4 + 2) = h23;
            *(__half2*)(al + nn * AT_STR + kk4 * 4)     = l01;
            *(__half2*)(al + nn * AT_STR + kk4 * 4 + 2) = l23;
        }
        __syncthreads();

#pragma unroll
        for (int ks = 0; ks < 2; ks++) {
            const __half* wrow = w_s + (m0 + qr) * WO_STR + k0 + ks * 16 + 2 * qc;
            unsigned a0 = *(const unsigned*)wrow;
            unsigned a1 = *(const unsigned*)(wrow + 8 * WO_STR);
            unsigned a2 = *(const unsigned*)(wrow + 8);
            unsigned a3 = *(const unsigned*)(wrow + 8 * WO_STR + 8);
#pragma unroll
            for (int nt = 0; nt < 4; nt++) {
                const __half* bh = ah + (n0w + nt * 8 + qr) * AT_STR + ks * 16 + 2 * qc;
                const __half* bl = al + (n0w + nt * 8 + qr) * AT_STR + ks * 16 + 2 * qc;
                unsigned b0 = *(const unsigned*)bh;
                unsigned b1 = *(const unsigned*)(bh + 8);
                mma_f16(acc[nt][0], acc[nt][1], acc[nt][2], acc[nt][3],
                        a0, a1, a2, a3, b0, b1);
                unsigned c0 = *(const unsigned*)bl;
                unsigned c1 = *(const unsigned*)(bl + 8);
                mma_f16(acc[nt][0], acc[nt][1], acc[nt][2], acc[nt][3],
                        a0, a1, a2, a3, c0, c1);
            }
        }
    }

#pragma unroll
    for (int rr = 0; rr < 2; rr++) {
        int c = Cbase + m0 + qr + rr * 8;
        float bias = bo[c];
#pragma unroll
        for (int nt = 0; nt < 4; nt++) {
            int n = N0 + n0w + qc * 2 + nt * 8;
            size_t idx = ((size_t)b * C_ + c) * N_ + n;
            float2 xv = *(const float2*)(x + idx);
            *(float2*)(out + idx) = make_float2(
                acc[nt][rr * 2] + bias + xv.x,
                acc[nt][rr * 2 + 1] + bias + xv.y);
        }
    }
}

// ============================================================================
extern "C" void kernel_launch(void* const* d_in, const int* in_sizes, int n_in,
                              void* d_out, int out_size) {
    (void)in_sizes; (void)n_in; (void)out_size;
    const float* x  = (const float*)d_in[0];
    const float* wt = (const float*)d_in[1];
    const float* bt = (const float*)d_in[2];
    const float* wp = (const float*)d_in[3];
    const float* bp = (const float*)d_in[4];
    const float* wg = (const float*)d_in[5];
    const float* bg = (const float*)d_in[6];
    const float* wo = (const float*)d_in[7];
    const float* bo = (const float*)d_in[8];
    float* out = (float*)d_out;

    const int smem_proj  = (32 * 36 + 2 * 32 * 136) * 4;         // 39424
    const int smem_flash = (64 * PHI_STR + 128 * G_STR) * 2;     // 23552
    const int smem_out   = (32 * WO_STR + 2 * 128 * AT_STR) * 2; // 29184

    cudaFuncSetAttribute(proj_tc_kernel,
                         cudaFuncAttributeMaxDynamicSharedMemorySize, smem_proj);
    cudaFuncSetAttribute(flash_tc_kernel,
                         cudaFuncAttributeMaxDynamicSharedMemorySize, smem_flash);
    cudaFuncSetAttribute(out_tc_kernel,
                         cudaFuncAttributeMaxDynamicSharedMemorySize, smem_out);

    proj_tc_kernel<<<dim3(192, B_), 256, smem_proj>>>(x, wt, bt, wp, bp, wg, bg);
    flash_tc_kernel<<<dim3(N_ / 64, B_), 128, smem_flash>>>();
    out_tc_kernel<<<dim3(256, B_), 256, smem_out>>>(wo, bo, x, out);
}

// round 12
// speedup vs baseline: 1.1462x; 1.0488x over previous
#include <cuda_runtime.h>
#include <cuda_fp16.h>

// NonLocalAttention: B=4, C=256, H=W=64 -> N=4096, C8=32, C2=128
//   proj_tc_kernel : projections (tf32 mma, split-x), 96 outs/CTA (3 Mgroups
//                    merged: B-fragments + x staging amortized), fp16 out
//   flash_tc_kernel: fp16 m16n8k16 flash attention (exact R9/R11)
//   out_tc_kernel  : w_o @ att + b_o + x (fp16 mma, split-att) (exact R11)

#define B_ 4
#define C_ 256
#define N_ 4096
#define C8_ 32
#define C2_ 128

__device__ __half d_theta[(size_t)B_ * C8_ * N_];   // theta * log2e
__device__ __half d_phi[(size_t)B_ * C8_ * N_];
__device__ __half d_g[(size_t)B_ * C2_ * N_];       // [b][c2][n]
__device__ float  d_att[(size_t)B_ * N_ * C2_];

// ---- intrinsics ----
__device__ __forceinline__ unsigned cvt_tf32(float x) {
    unsigned r;
    asm("cvt.rna.tf32.f32 %0, %1;" : "=r"(r) : "f"(x));
    return r;
}
__device__ __forceinline__ float cvt_tf32f(float x) {
    return __uint_as_float(cvt_tf32(x));
}
__device__ __forceinline__ float ex2f(float x) {
    float r;
    asm("ex2.approx.f32 %0, %1;" : "=f"(r) : "f"(x));
    return r;
}
__device__ __forceinline__ void mma_tf32(
    float& c0, float& c1, float& c2, float& c3,
    unsigned a0, unsigned a1, unsigned a2, unsigned a3,
    unsigned b0, unsigned b1) {
    asm("mma.sync.aligned.m16n8k8.row.col.f32.tf32.tf32.f32 "
        "{%0,%1,%2,%3}, {%4,%5,%6,%7}, {%8,%9}, {%0,%1,%2,%3};"
        : "+f"(c0), "+f"(c1), "+f"(c2), "+f"(c3)
        : "r"(a0), "r"(a1), "r"(a2), "r"(a3), "r"(b0), "r"(b1));
}
__device__ __forceinline__ void mma_f16(
    float& c0, float& c1, float& c2, float& c3,
    unsigned a0, unsigned a1, unsigned a2, unsigned a3,
    unsigned b0, unsigned b1) {
    asm("mma.sync.aligned.m16n8k16.row.col.f32.f16.f16.f32 "
        "{%0,%1,%2,%3}, {%4,%5,%6,%7}, {%8,%9}, {%0,%1,%2,%3};"
        : "+f"(c0), "+f"(c1), "+f"(c2), "+f"(c3)
        : "r"(a0), "r"(a1), "r"(a2), "r"(a3), "r"(b0), "r"(b1));
}
__device__ __forceinline__ unsigned packh2(float lo, float hi) {
    __half2 h = __floats2half2_rn(lo, hi);
    return *(unsigned*)&h;
}

// ============================================================================
// Kernel 1: projections via tf32 mma, split-x. 96 outputs per CTA.
// Grid.x = 2 Mgroups(96) * 32 Ngroups(128) = 64, grid.y = B.
// ============================================================================
__global__ void __launch_bounds__(256) proj_tc_kernel(
    const float* __restrict__ x,
    const float* __restrict__ wt, const float* __restrict__ bt,
    const float* __restrict__ wp, const float* __restrict__ bp,
    const float* __restrict__ wg, const float* __restrict__ bg) {
    extern __shared__ float sm[];
    float* ws = sm;                 // [96][36]
    float* xh = sm + 96 * 36;       // [32][136]
    float* xl = xh + 32 * 136;      // [32][136]

    const int b  = blockIdx.y;
    const int Mbase = (blockIdx.x >> 5) * 96;
    const int N0    = (blockIdx.x & 31) * 128;
    const int tid  = threadIdx.x;
    const int wid  = tid >> 5, lane = tid & 31;
    const int m0   = (wid >> 2) * 16;
    const int n0w  = (wid & 3) * 32;
    const int qr = lane >> 2, qc = lane & 3;

    float acc[3][4][4];
#pragma unroll
    for (int mt = 0; mt < 3; mt++)
#pragma unroll
        for (int nt = 0; nt < 4; nt++)
#pragma unroll
            for (int j = 0; j < 4; j++) acc[mt][nt][j] = 0.f;

    for (int kp = 0; kp < 8; kp++) {
        const int k0 = kp * 32;
        __syncthreads();
        // stage weights [96 o][32 k] -> tf32(rna)
#pragma unroll
        for (int i = 0; i < 12; i++) {
            int idx = i * 256 + tid;           // 0..3071
            int r = idx >> 5, kk = idx & 31;
            int o = Mbase + r;
            const float* src = (o < 32) ? wt + o * C_
                             : (o < 64) ? wp + (o - 32) * C_
                                        : wg + (o - 64) * C_;
            ws[r * 36 + kk] = cvt_tf32f(src[k0 + kk]);
        }
        // stage x [32 c][128 n], split hi/lo
#pragma unroll
        for (int i = 0; i < 4; i++) {
            int idx = i * 256 + tid;           // 0..1023
            int cc = idx >> 5, nn4 = idx & 31;
            float4 v = *(const float4*)(
                x + ((size_t)(b * C_ + k0 + cc)) * N_ + N0 + nn4 * 4);
            float4 h, l;
            h.x = cvt_tf32f(v.x); l.x = v.x - h.x;
            h.y = cvt_tf32f(v.y); l.y = v.y - h.y;
            h.z = cvt_tf32f(v.z); l.z = v.z - h.z;
            h.w = cvt_tf32f(v.w); l.w = v.w - h.w;
            *(float4*)(xh + cc * 136 + nn4 * 4) = h;
            *(float4*)(xl + cc * 136 + nn4 * 4) = l;
        }
        __syncthreads();

#pragma unroll
        for (int ks = 0; ks < 4; ks++) {
            // load B fragments once, reuse across 3 m-tiles
            const float* bh = xh + (ks * 8 + qc) * 136 + n0w + qr;
            const float* bl = xl + (ks * 8 + qc) * 136 + n0w + qr;
            unsigned bh0[4], bh1[4], bl0[4], bl1[4];
#pragma unroll
            for (int nt = 0; nt < 4; nt++) {
                bh0[nt] = __float_as_uint(bh[nt * 8]);
                bh1[nt] = __float_as_uint(bh[4 * 136 + nt * 8]);
                bl0[nt] = __float_as_uint(bl[nt * 8]);
                bl1[nt] = __float_as_uint(bl[4 * 136 + nt * 8]);
            }
#pragma unroll
            for (int mt = 0; mt < 3; mt++) {
                const float* wrow = ws + (mt * 32 + m0 + qr) * 36 + ks * 8 + qc;
                unsigned a0 = __float_as_uint(wrow[0]);
                unsigned a1 = __float_as_uint(wrow[8 * 36]);
                unsigned a2 = __float_as_uint(wrow[4]);
                unsigned a3 = __float_as_uint(wrow[8 * 36 + 4]);
#pragma unroll
                for (int nt = 0; nt < 4; nt++) {
                    mma_tf32(acc[mt][nt][0], acc[mt][nt][1],
                             acc[mt][nt][2], acc[mt][nt][3],
                             a0, a1, a2, a3, bh0[nt], bh1[nt]);
                    mma_tf32(acc[mt][nt][0], acc[mt][nt][1],
                             acc[mt][nt][2], acc[mt][nt][3],
                             a0, a1, a2, a3, bl0[nt], bl1[nt]);
                }
            }
        }
    }

    const float LOG2E = 1.4426950408889634f;
#pragma unroll
    for (int mt = 0; mt < 3; mt++) {
#pragma unroll
        for (int rr = 0; rr < 2; rr++) {
            int o = Mbase + mt * 32 + m0 + qr + rr * 8;
            if (o < 32) {
                float bias = bt[o];
                __half2* dst = (__half2*)(d_theta + ((size_t)b * C8_ + o) * N_ +
                                          N0 + n0w + qc * 2);
#pragma unroll
                for (int nt = 0; nt < 4; nt++)
                    dst[nt * 4] = __floats2half2_rn(
                        (acc[mt][nt][rr * 2] + bias) * LOG2E,
                        (acc[mt][nt][rr * 2 + 1] + bias) * LOG2E);
            } else if (o < 64) {
                float bias = bp[o - 32];
                __half2* dst = (__half2*)(d_phi + ((size_t)b * C8_ + (o - 32)) * N_ +
                                          N0 + n0w + qc * 2);
#pragma unroll
                for (int nt = 0; nt < 4; nt++)
                    dst[nt * 4] = __floats2half2_rn(
                        acc[mt][nt][rr * 2] + bias, acc[mt][nt][rr * 2 + 1] + bias);
            } else {
                float bias = bg[o - 64];
                __half2* dst = (__half2*)(d_g + ((size_t)b * C2_ + (o - 64)) * N_ +
                                          N0 + n0w + qc * 2);
#pragma unroll
                for (int nt = 0; nt < 4; nt++)
                    dst[nt * 4] = __floats2half2_rn(
                        acc[mt][nt][rr * 2] + bias, acc[mt][nt][rr * 2 + 1] + bias);
            }
        }
    }
}

// ============================================================================
// Kernel 2: fp16 flash attention — EXACT R9/R11 (lb(128,2)).
// ============================================================================
#define PHI_STR 40
#define G_STR   72

__global__ void __launch_bounds__(128, 2) flash_tc_kernel() {
    extern __shared__ __half smh[];
    __half* phi_s = smh;                     // 64*40 halves
    __half* g_s   = smh + 64 * PHI_STR;      // 128*72 halves

    const int b   = blockIdx.y;
    const int q0  = blockIdx.x * 64;
    const int tid = threadIdx.x;
    const int w    = tid >> 5;
    const int lane = tid & 31;
    const int qr = lane >> 2;
    const int qc = lane & 3;
    const int row0 = q0 + w * 16 + qr;

    unsigned at[2][4];
    {
        const __half* tp = d_theta + (size_t)b * C8_ * N_;
#pragma unroll
        for (int ks = 0; ks < 2; ks++) {
            int c = ks * 16 + 2 * qc;
            at[ks][0] = packh2(__half2float(tp[(size_t)c * N_ + row0]),
                               __half2float(tp[(size_t)(c + 1) * N_ + row0]));
            at[ks][1] = packh2(__half2float(tp[(size_t)c * N_ + row0 + 8]),
                               __half2float(tp[(size_t)(c + 1) * N_ + row0 + 8]));
            at[ks][2] = packh2(__half2float(tp[(size_t)(c + 8) * N_ + row0]),
                               __half2float(tp[(size_t)(c + 9) * N_ + row0]));
            at[ks][3] = packh2(__half2float(tp[(size_t)(c + 8) * N_ + row0 + 8]),
                               __half2float(tp[(size_t)(c + 9) * N_ + row0 + 8]));
        }
    }

    float O[16][4];
#pragma unroll
    for (int nt = 0; nt < 16; nt++)
#pragma unroll
        for (int j = 0; j < 4; j++) O[nt][j] = 0.f;
    float m0 = -1e30f, m1 = -1e30f, l0 = 0.f, l1 = 0.f;

    for (int kt = 0; kt < N_; kt += 64) {
        __syncthreads();
#pragma unroll
        for (int i = 0; i < 8; i++) {
            int idx = i * 128 + tid;
            int c = idx >> 5, kc = idx & 31;
            __half2 v = *(const __half2*)(
                d_phi + ((size_t)b * C8_ + c) * N_ + kt + kc * 2);
            phi_s[(kc * 2) * PHI_STR + c]     = __low2half(v);
            phi_s[(kc * 2 + 1) * PHI_STR + c] = __high2half(v);
        }
#pragma unroll
        for (int i = 0; i < 16; i++) {
            int idx = i * 128 + tid;
            int c2 = idx >> 4, kq = idx & 15;
            uint2 v = *(const uint2*)(
                d_g + ((size_t)b * C2_ + c2) * N_ + kt + kq * 4);
            *(uint2*)(g_s + c2 * G_STR + kq * 4) = v;
        }
        __syncthreads();

        float s[8][4];
#pragma unroll
        for (int nt = 0; nt < 8; nt++)
#pragma unroll
            for (int j = 0; j < 4; j++) s[nt][j] = 0.f;

#pragma unroll
        for (int ks = 0; ks < 2; ks++) {
#pragma unroll
            for (int nt = 0; nt < 8; nt++) {
                const __half* pb = phi_s + (nt * 8 + qr) * PHI_STR + ks * 16 + 2 * qc;
                unsigned b0 = *(const unsigned*)pb;
                unsigned b1 = *(const unsigned*)(pb + 8);
                mma_f16(s[nt][0], s[nt][1], s[nt][2], s[nt][3],
                        at[ks][0], at[ks][1], at[ks][2], at[ks][3], b0, b1);
            }
        }

        float rm0 = -1e30f, rm1 = -1e30f;
#pragma unroll
        for (int nt = 0; nt < 8; nt++) {
            rm0 = fmaxf(rm0, fmaxf(s[nt][0], s[nt][1]));
            rm1 = fmaxf(rm1, fmaxf(s[nt][2], s[nt][3]));
        }
        rm0 = fmaxf(rm0, __shfl_xor_sync(0xffffffffu, rm0, 1, 4));
        rm0 = fmaxf(rm0, __shfl_xor_sync(0xffffffffu, rm0, 2, 4));
        rm1 = fmaxf(rm1, __shfl_xor_sync(0xffffffffu, rm1, 1, 4));
        rm1 = fmaxf(rm1, __shfl_xor_sync(0xffffffffu, rm1, 2, 4));
        float mn0 = fmaxf(m0, rm0), mn1 = fmaxf(m1, rm1);
        float cr0 = ex2f(m0 - mn0), cr1 = ex2f(m1 - mn1);
        m0 = mn0; m1 = mn1;
#pragma unroll
        for (int nt = 0; nt < 16; nt++) {
            O[nt][0] *= cr0; O[nt][1] *= cr0;
            O[nt][2] *= cr1; O[nt][3] *= cr1;
        }

        unsigned pk[8][2];
        float rs0 = 0.f, rs1 = 0.f;
#pragma unroll
        for (int nt = 0; nt < 8; nt++) {
            float e0 = ex2f(s[nt][0] - mn0);
            float e1 = ex2f(s[nt][1] - mn0);
            float e2 = ex2f(s[nt][2] - mn1);
            float e3 = ex2f(s[nt][3] - mn1);
            rs0 += e0 + e1; rs1 += e2 + e3;
            pk[nt][0] = packh2(e0, e1);
            pk[nt][1] = packh2(e2, e3);
        }
        l0 = l0 * cr0 + rs0;
        l1 = l1 * cr1 + rs1;

#pragma unroll
        for (int kb = 0; kb < 4; kb++) {
            unsigned a0 = pk[2 * kb][0];
            unsigned a1 = pk[2 * kb][1];
            unsigned a2 = pk[2 * kb + 1][0];
            unsigned a3 = pk[2 * kb + 1][1];
#pragma unroll
            for (int nt = 0; nt < 16; nt++) {
                const __half* gb = g_s + (nt * 8 + qr) * G_STR + kb * 16 + 2 * qc;
                unsigned b0 = *(const unsigned*)gb;
                unsigned b1 = *(const unsigned*)(gb + 8);
                mma_f16(O[nt][0], O[nt][1], O[nt][2], O[nt][3],
                        a0, a1, a2, a3, b0, b1);
            }
        }
    }

    l0 += __shfl_xor_sync(0xffffffffu, l0, 1, 4);
    l0 += __shfl_xor_sync(0xffffffffu, l0, 2, 4);
    l1 += __shfl_xor_sync(0xffffffffu, l1, 1, 4);
    l1 += __shfl_xor_sync(0xffffffffu, l1, 2, 4);
    float inv0 = 1.0f / l0;
    float inv1 = 1.0f / l1;

    float* dst0 = d_att + ((size_t)b * N_ + row0) * C2_ + qc * 2;
#pragma unroll
    for (int nt = 0; nt < 16; nt++) {
        *(float2*)(dst0 + nt * 8) =
            make_float2(O[nt][0] * inv0, O[nt][1] * inv0);
        *(float2*)(dst0 + 8 * C2_ + nt * 8) =
            make_float2(O[nt][2] * inv1, O[nt][3] * inv1);
    }
}

// ============================================================================
// Kernel 3: out = w_o @ att + b_o + x via fp16 mma, split-att. (exact R11)
// ============================================================================
#define WO_STR 136
#define AT_STR 40

__global__ void __launch_bounds__(256) out_tc_kernel(
    const float* __restrict__ wo, const float* __restrict__ bo,
    const float* __restrict__ x, float* __restrict__ out) {
    extern __shared__ __half smh[];
    __half* w_s = smh;                       // [32][WO_STR]
    __half* ah  = smh + 32 * WO_STR;         // [128][AT_STR]
    __half* al  = ah + 128 * AT_STR;         // [128][AT_STR]

    const int b  = blockIdx.y;
    const int Cbase = (blockIdx.x >> 5) * 32;
    const int N0    = (blockIdx.x & 31) * 128;
    const int tid  = threadIdx.x;
    const int wid  = tid >> 5, lane = tid & 31;
    const int m0   = (wid >> 2) * 16;
    const int n0w  = (wid & 3) * 32;
    const int qr = lane >> 2, qc = lane & 3;

#pragma unroll
    for (int i = 0; i < 16; i++) {
        int idx = i * 256 + tid;
        int r = idx >> 7, kk = idx & 127;
        w_s[r * WO_STR + kk] = __float2half_rn(wo[(Cbase + r) * C2_ + kk]);
    }

    float acc[4][4];
#pragma unroll
    for (int nt = 0; nt < 4; nt++)
#pragma unroll
        for (int j = 0; j < 4; j++) acc[nt][j] = 0.f;

    for (int kp = 0; kp < 4; kp++) {
        const int k0 = kp * 32;
        __syncthreads();
#pragma unroll
        for (int i = 0; i < 4; i++) {
            int idx = i * 256 + tid;
            int nn = idx >> 3, kk4 = idx & 7;
            float4 v = *(const float4*)(
                d_att + ((size_t)b * N_ + N0 + nn) * C2_ + k0 + kk4 * 4);
            __half2 h01 = __floats2half2_rn(v.x, v.y);
            __half2 h23 = __floats2half2_rn(v.z, v.w);
            __half2 l01 = __floats2half2_rn(v.x - __half2float(__low2half(h01)),
                                            v.y - __half2float(__high2half(h01)));
            __half2 l23 = __floats2half2_rn(v.z - __half2float(__low2half(h23)),
                                            v.w - __half2float(__high2half(h23)));
            *(__half2*)(ah + nn * AT_STR + kk4 * 4)     = h01;
            *(__half2*)(ah + nn * AT_STR + kk4 * 4 + 2) = h23;
            *(__half2*)(al + nn * AT_STR + kk4 * 4)     = l01;
            *(__half2*)(al + nn * AT_STR + kk4 * 4 + 2) = l23;
        }
        __syncthreads();

#pragma unroll
        for (int ks = 0; ks < 2; ks++) {
            const __half* wrow = w_s + (m0 + qr) * WO_STR + k0 + ks * 16 + 2 * qc;
            unsigned a0 = *(const unsigned*)wrow;
            unsigned a1 = *(const unsigned*)(wrow + 8 * WO_STR);
            unsigned a2 = *(const unsigned*)(wrow + 8);
            unsigned a3 = *(const unsigned*)(wrow + 8 * WO_STR + 8);
#pragma unroll
            for (int nt = 0; nt < 4; nt++) {
                const __half* bh = ah + (n0w + nt * 8 + qr) * AT_STR + ks * 16 + 2 * qc;
                const __half* bl = al + (n0w + nt * 8 + qr) * AT_STR + ks * 16 + 2 * qc;
                unsigned b0 = *(const unsigned*)bh;
                unsigned b1 = *(const unsigned*)(bh + 8);
                mma_f16(acc[nt][0], acc[nt][1], acc[nt][2], acc[nt][3],
                        a0, a1, a2, a3, b0, b1);
                unsigned c0 = *(const unsigned*)bl;
                unsigned c1 = *(const unsigned*)(bl + 8);
                mma_f16(acc[nt][0], acc[nt][1], acc[nt][2], acc[nt][3],
                        a0, a1, a2, a3, c0, c1);
            }
        }
    }

#pragma unroll
    for (int rr = 0; rr < 2; rr++) {
        int c = Cbase + m0 + qr + rr * 8;
        float bias = bo[c];
#pragma unroll
        for (int nt = 0; nt < 4; nt++) {
            int n = N0 + n0w + qc * 2 + nt * 8;
            size_t idx = ((size_t)b * C_ + c) * N_ + n;
            float2 xv = *(const float2*)(x + idx);
            *(float2*)(out + idx) = make_float2(
                acc[nt][rr * 2] + bias + xv.x,
                acc[nt][rr * 2 + 1] + bias + xv.y);
        }
    }
}

// ============================================================================
extern "C" void kernel_launch(void* const* d_in, const int* in_sizes, int n_in,
                              void* d_out, int out_size) {
    (void)in_sizes; (void)n_in; (void)out_size;
    const float* x  = (const float*)d_in[0];
    const float* wt = (const float*)d_in[1];
    const float* bt = (const float*)d_in[2];
    const float* wp = (const float*)d_in[3];
    const float* bp = (const float*)d_in[4];
    const float* wg = (const float*)d_in[5];
    const float* bg = (const float*)d_in[6];
    const float* wo = (const float*)d_in[7];
    const float* bo = (const float*)d_in[8];
    float* out = (float*)d_out;

    const int smem_proj  = (96 * 36 + 2 * 32 * 136) * 4;         // 48640
    const int smem_flash = (64 * PHI_STR + 128 * G_STR) * 2;     // 23552
    const int smem_out   = (32 * WO_STR + 2 * 128 * AT_STR) * 2; // 29184

    cudaFuncSetAttribute(proj_tc_kernel,
                         cudaFuncAttributeMaxDynamicSharedMemorySize, smem_proj);
    cudaFuncSetAttribute(flash_tc_kernel,
                         cudaFuncAttributeMaxDynamicSharedMemorySize, smem_flash);
    cudaFuncSetAttribute(out_tc_kernel,
                         cudaFuncAttributeMaxDynamicSharedMemorySize, smem_out);

    proj_tc_kernel<<<dim3(64, B_), 256, smem_proj>>>(x, wt, bt, wp, bp, wg, bg);
    flash_tc_kernel<<<dim3(N_ / 64, B_), 128, smem_flash>>>();
    out_tc_kernel<<<dim3(256, B_), 256, smem_out>>>(wo, bo, x, out);
}

// round 14
// speedup vs baseline: 1.2135x; 1.0587x over previous
#include <cuda_runtime.h>
#include <cuda_fp16.h>

// NonLocalAttention: B=4, C=256, H=W=64 -> N=4096, C8=32, C2=128
//   proj_tc_kernel : projections (tf32 mma, split-x), 96 outs/CTA (exact R12)
//   flash_tc_kernel: fp16 flash attention, double-buffered staging (64 tiles!)
//   out_tc_kernel  : w_o @ att + b_o + x (fp16 mma, split-att) (exact R11)

#define B_ 4
#define C_ 256
#define N_ 4096
#define C8_ 32
#define C2_ 128

__device__ __half d_theta[(size_t)B_ * C8_ * N_];   // theta * log2e
__device__ __half d_phi[(size_t)B_ * C8_ * N_];
__device__ __half d_g[(size_t)B_ * C2_ * N_];       // [b][c2][n]
__device__ float  d_att[(size_t)B_ * N_ * C2_];

// ---- intrinsics ----
__device__ __forceinline__ unsigned cvt_tf32(float x) {
    unsigned r;
    asm("cvt.rna.tf32.f32 %0, %1;" : "=r"(r) : "f"(x));
    return r;
}
__device__ __forceinline__ float cvt_tf32f(float x) {
    return __uint_as_float(cvt_tf32(x));
}
__device__ __forceinline__ float ex2f(float x) {
    float r;
    asm("ex2.approx.f32 %0, %1;" : "=f"(r) : "f"(x));
    return r;
}
__device__ __forceinline__ void mma_tf32(
    float& c0, float& c1, float& c2, float& c3,
    unsigned a0, unsigned a1, unsigned a2, unsigned a3,
    unsigned b0, unsigned b1) {
    asm("mma.sync.aligned.m16n8k8.row.col.f32.tf32.tf32.f32 "
        "{%0,%1,%2,%3}, {%4,%5,%6,%7}, {%8,%9}, {%0,%1,%2,%3};"
        : "+f"(c0), "+f"(c1), "+f"(c2), "+f"(c3)
        : "r"(a0), "r"(a1), "r"(a2), "r"(a3), "r"(b0), "r"(b1));
}
__device__ __forceinline__ void mma_f16(
    float& c0, float& c1, float& c2, float& c3,
    unsigned a0, unsigned a1, unsigned a2, unsigned a3,
    unsigned b0, unsigned b1) {
    asm("mma.sync.aligned.m16n8k16.row.col.f32.f16.f16.f32 "
        "{%0,%1,%2,%3}, {%4,%5,%6,%7}, {%8,%9}, {%0,%1,%2,%3};"
        : "+f"(c0), "+f"(c1), "+f"(c2), "+f"(c3)
        : "r"(a0), "r"(a1), "r"(a2), "r"(a3), "r"(b0), "r"(b1));
}
__device__ __forceinline__ unsigned packh2(float lo, float hi) {
    __half2 h = __floats2half2_rn(lo, hi);
    return *(unsigned*)&h;
}

// ============================================================================
// Kernel 1: projections via tf32 mma, split-x. 96 outputs per CTA. (exact R12)
// ============================================================================
__global__ void __launch_bounds__(256) proj_tc_kernel(
    const float* __restrict__ x,
    const float* __restrict__ wt, const float* __restrict__ bt,
    const float* __restrict__ wp, const float* __restrict__ bp,
    const float* __restrict__ wg, const float* __restrict__ bg) {
    extern __shared__ float sm[];
    float* ws = sm;                 // [96][36]
    float* xh = sm + 96 * 36;       // [32][136]
    float* xl = xh + 32 * 136;      // [32][136]

    const int b  = blockIdx.y;
    const int Mbase = (blockIdx.x >> 5) * 96;
    const int N0    = (blockIdx.x & 31) * 128;
    const int tid  = threadIdx.x;
    const int wid  = tid >> 5, lane = tid & 31;
    const int m0   = (wid >> 2) * 16;
    const int n0w  = (wid & 3) * 32;
    const int qr = lane >> 2, qc = lane & 3;

    float acc[3][4][4];
#pragma unroll
    for (int mt = 0; mt < 3; mt++)
#pragma unroll
        for (int nt = 0; nt < 4; nt++)
#pragma unroll
            for (int j = 0; j < 4; j++) acc[mt][nt][j] = 0.f;

    for (int kp = 0; kp < 8; kp++) {
        const int k0 = kp * 32;
        __syncthreads();
#pragma unroll
        for (int i = 0; i < 12; i++) {
            int idx = i * 256 + tid;
            int r = idx >> 5, kk = idx & 31;
            int o = Mbase + r;
            const float* src = (o < 32) ? wt + o * C_
                             : (o < 64) ? wp + (o - 32) * C_
                                        : wg + (o - 64) * C_;
            ws[r * 36 + kk] = cvt_tf32f(src[k0 + kk]);
        }
#pragma unroll
        for (int i = 0; i < 4; i++) {
            int idx = i * 256 + tid;
            int cc = idx >> 5, nn4 = idx & 31;
            float4 v = *(const float4*)(
                x + ((size_t)(b * C_ + k0 + cc)) * N_ + N0 + nn4 * 4);
            float4 h, l;
            h.x = cvt_tf32f(v.x); l.x = v.x - h.x;
            h.y = cvt_tf32f(v.y); l.y = v.y - h.y;
            h.z = cvt_tf32f(v.z); l.z = v.z - h.z;
            h.w = cvt_tf32f(v.w); l.w = v.w - h.w;
            *(float4*)(xh + cc * 136 + nn4 * 4) = h;
            *(float4*)(xl + cc * 136 + nn4 * 4) = l;
        }
        __syncthreads();

#pragma unroll
        for (int ks = 0; ks < 4; ks++) {
            const float* bh = xh + (ks * 8 + qc) * 136 + n0w + qr;
            const float* bl = xl + (ks * 8 + qc) * 136 + n0w + qr;
            unsigned bh0[4], bh1[4], bl0[4], bl1[4];
#pragma unroll
            for (int nt = 0; nt < 4; nt++) {
                bh0[nt] = __float_as_uint(bh[nt * 8]);
                bh1[nt] = __float_as_uint(bh[4 * 136 + nt * 8]);
                bl0[nt] = __float_as_uint(bl[nt * 8]);
                bl1[nt] = __float_as_uint(bl[4 * 136 + nt * 8]);
            }
#pragma unroll
            for (int mt = 0; mt < 3; mt++) {
                const float* wrow = ws + (mt * 32 + m0 + qr) * 36 + ks * 8 + qc;
                unsigned a0 = __float_as_uint(wrow[0]);
                unsigned a1 = __float_as_uint(wrow[8 * 36]);
                unsigned a2 = __float_as_uint(wrow[4]);
                unsigned a3 = __float_as_uint(wrow[8 * 36 + 4]);
#pragma unroll
                for (int nt = 0; nt < 4; nt++) {
                    mma_tf32(acc[mt][nt][0], acc[mt][nt][1],
                             acc[mt][nt][2], acc[mt][nt][3],
                             a0, a1, a2, a3, bh0[nt], bh1[nt]);
                    mma_tf32(acc[mt][nt][0], acc[mt][nt][1],
                             acc[mt][nt][2], acc[mt][nt][3],
                             a0, a1, a2, a3, bl0[nt], bl1[nt]);
                }
            }
        }
    }

    const float LOG2E = 1.4426950408889634f;
#pragma unroll
    for (int mt = 0; mt < 3; mt++) {
#pragma unroll
        for (int rr = 0; rr < 2; rr++) {
            int o = Mbase + mt * 32 + m0 + qr + rr * 8;
            if (o < 32) {
                float bias = bt[o];
                __half2* dst = (__half2*)(d_theta + ((size_t)b * C8_ + o) * N_ +
                                          N0 + n0w + qc * 2);
#pragma unroll
                for (int nt = 0; nt < 4; nt++)
                    dst[nt * 4] = __floats2half2_rn(
                        (acc[mt][nt][rr * 2] + bias) * LOG2E,
                        (acc[mt][nt][rr * 2 + 1] + bias) * LOG2E);
            } else if (o < 64) {
                float bias = bp[o - 32];
                __half2* dst = (__half2*)(d_phi + ((size_t)b * C8_ + (o - 32)) * N_ +
                                          N0 + n0w + qc * 2);
#pragma unroll
                for (int nt = 0; nt < 4; nt++)
                    dst[nt * 4] = __floats2half2_rn(
                        acc[mt][nt][rr * 2] + bias, acc[mt][nt][rr * 2 + 1] + bias);
            } else {
                float bias = bg[o - 64];
                __half2* dst = (__half2*)(d_g + ((size_t)b * C2_ + (o - 64)) * N_ +
                                          N0 + n0w + qc * 2);
#pragma unroll
                for (int nt = 0; nt < 4; nt++)
                    dst[nt * 4] = __floats2half2_rn(
                        acc[mt][nt][rr * 2] + bias, acc[mt][nt][rr * 2 + 1] + bias);
            }
        }
    }
}

// ============================================================================
// Kernel 2: fp16 flash attention, double-buffered staging. 64 key tiles.
// ============================================================================
#define PHI_STR 40
#define G_STR   72
#define PHI_BUF (64 * PHI_STR)
#define G_BUF   (128 * G_STR)
#define NTILES  (N_ / 64)

__global__ void __launch_bounds__(128, 2) flash_tc_kernel() {
    extern __shared__ __half smh[];
    // layout: phi[0], phi[1], g[0], g[1]
    __half* g_base = smh + 2 * PHI_BUF;

    const int b   = blockIdx.y;
    const int q0  = blockIdx.x * 64;
    const int tid = threadIdx.x;
    const int w    = tid >> 5;
    const int lane = tid & 31;
    const int qr = lane >> 2;
    const int qc = lane & 3;
    const int row0 = q0 + w * 16 + qr;

    unsigned at[2][4];
    {
        const __half* tp = d_theta + (size_t)b * C8_ * N_;
#pragma unroll
        for (int ks = 0; ks < 2; ks++) {
            int c = ks * 16 + 2 * qc;
            at[ks][0] = packh2(__half2float(tp[(size_t)c * N_ + row0]),
                               __half2float(tp[(size_t)(c + 1) * N_ + row0]));
            at[ks][1] = packh2(__half2float(tp[(size_t)c * N_ + row0 + 8]),
                               __half2float(tp[(size_t)(c + 1) * N_ + row0 + 8]));
            at[ks][2] = packh2(__half2float(tp[(size_t)(c + 8) * N_ + row0]),
                               __half2float(tp[(size_t)(c + 9) * N_ + row0]));
            at[ks][3] = packh2(__half2float(tp[(size_t)(c + 8) * N_ + row0 + 8]),
                               __half2float(tp[(size_t)(c + 9) * N_ + row0 + 8]));
        }
    }

    float O[16][4];
#pragma unroll
    for (int nt = 0; nt < 16; nt++)
#pragma unroll
        for (int j = 0; j < 4; j++) O[nt][j] = 0.f;
    float m0 = -1e30f, m1 = -1e30f, l0 = 0.f, l1 = 0.f;

    // ---- prologue: stage tile 0 into buffer 0 ----
    {
        __half* phi_s = smh;
        __half* g_s   = g_base;
#pragma unroll
        for (int i = 0; i < 8; i++) {
            int idx = i * 128 + tid;
            int c = idx >> 5, kc = idx & 31;
            __half2 v = *(const __half2*)(
                d_phi + ((size_t)b * C8_ + c) * N_ + kc * 2);
            phi_s[(kc * 2) * PHI_STR + c]     = __low2half(v);
            phi_s[(kc * 2 + 1) * PHI_STR + c] = __high2half(v);
        }
#pragma unroll
        for (int i = 0; i < 16; i++) {
            int idx = i * 128 + tid;
            int c2 = idx >> 4, kq = idx & 15;
            uint2 v = *(const uint2*)(
                d_g + ((size_t)b * C2_ + c2) * N_ + kq * 4);
            *(uint2*)(g_s + c2 * G_STR + kq * 4) = v;
        }
    }
    __syncthreads();

    for (int it = 0; it < NTILES; it++) {
        const int cur = it & 1;
        __half* phi_s = smh + cur * PHI_BUF;
        __half* g_s   = g_base + cur * G_BUF;
        __half* phi_n = smh + (1 - cur) * PHI_BUF;
        __half* g_n   = g_base + (1 - cur) * G_BUF;

        // ---- prefetch LDGs for tile it+1 (into registers) ----
        __half2 pre_phi[8];
        uint2   pre_g[16];
        const bool has_next = (it < NTILES - 1);
        if (has_next) {
            const int kt2 = (it + 1) * 64;
#pragma unroll
            for (int i = 0; i < 8; i++) {
                int idx = i * 128 + tid;
                int c = idx >> 5, kc = idx & 31;
                pre_phi[i] = *(const __half2*)(
                    d_phi + ((size_t)b * C8_ + c) * N_ + kt2 + kc * 2);
            }
#pragma unroll
            for (int i = 0; i < 16; i++) {
                int idx = i * 128 + tid;
                int c2 = idx >> 4, kq = idx & 15;
                pre_g[i] = *(const uint2*)(
                    d_g + ((size_t)b * C2_ + c2) * N_ + kt2 + kq * 4);
            }
        }

        // ---- GEMM1: S = theta @ phi^T ----
        float s[8][4];
#pragma unroll
        for (int nt = 0; nt < 8; nt++)
#pragma unroll
            for (int j = 0; j < 4; j++) s[nt][j] = 0.f;

#pragma unroll
        for (int ks = 0; ks < 2; ks++) {
#pragma unroll
            for (int nt = 0; nt < 8; nt++) {
                const __half* pb = phi_s + (nt * 8 + qr) * PHI_STR + ks * 16 + 2 * qc;
                unsigned b0 = *(const unsigned*)pb;
                unsigned b1 = *(const unsigned*)(pb + 8);
                mma_f16(s[nt][0], s[nt][1], s[nt][2], s[nt][3],
                        at[ks][0], at[ks][1], at[ks][2], at[ks][3], b0, b1);
            }
        }

        // ---- online-max softmax ----
        float rm0 = -1e30f, rm1 = -1e30f;
#pragma unroll
        for (int nt = 0; nt < 8; nt++) {
            rm0 = fmaxf(rm0, fmaxf(s[nt][0], s[nt][1]));
            rm1 = fmaxf(rm1, fmaxf(s[nt][2], s[nt][3]));
        }
        rm0 = fmaxf(rm0, __shfl_xor_sync(0xffffffffu, rm0, 1, 4));
        rm0 = fmaxf(rm0, __shfl_xor_sync(0xffffffffu, rm0, 2, 4));
        rm1 = fmaxf(rm1, __shfl_xor_sync(0xffffffffu, rm1, 1, 4));
        rm1 = fmaxf(rm1, __shfl_xor_sync(0xffffffffu, rm1, 2, 4));
        float mn0 = fmaxf(m0, rm0), mn1 = fmaxf(m1, rm1);
        float cr0 = ex2f(m0 - mn0), cr1 = ex2f(m1 - mn1);
        m0 = mn0; m1 = mn1;
#pragma unroll
        for (int nt = 0; nt < 16; nt++) {
            O[nt][0] *= cr0; O[nt][1] *= cr0;
            O[nt][2] *= cr1; O[nt][3] *= cr1;
        }

        unsigned pk[8][2];
        float rs0 = 0.f, rs1 = 0.f;
#pragma unroll
        for (int nt = 0; nt < 8; nt++) {
            float e0 = ex2f(s[nt][0] - mn0);
            float e1 = ex2f(s[nt][1] - mn0);
            float e2 = ex2f(s[nt][2] - mn1);
            float e3 = ex2f(s[nt][3] - mn1);
            rs0 += e0 + e1; rs1 += e2 + e3;
            pk[nt][0] = packh2(e0, e1);
            pk[nt][1] = packh2(e2, e3);
        }
        l0 = l0 * cr0 + rs0;
        l1 = l1 * cr1 + rs1;

        // ---- GEMM2: O += P @ g ----
#pragma unroll
        for (int kb = 0; kb < 4; kb++) {
            unsigned a0 = pk[2 * kb][0];
            unsigned a1 = pk[2 * kb][1];
            unsigned a2 = pk[2 * kb + 1][0];
            unsigned a3 = pk[2 * kb + 1][1];
#pragma unroll
            for (int nt = 0; nt < 16; nt++) {
                const __half* gb = g_s + (nt * 8 + qr) * G_STR + kb * 16 + 2 * qc;
                unsigned b0 = *(const unsigned*)gb;
                unsigned b1 = *(const unsigned*)(gb + 8);
                mma_f16(O[nt][0], O[nt][1], O[nt][2], O[nt][3],
                        a0, a1, a2, a3, b0, b1);
            }
        }

        // ---- STS prefetched tile into the other buffer ----
        if (has_next) {
#pragma unroll
            for (int i = 0; i < 8; i++) {
                int idx = i * 128 + tid;
                int c = idx >> 5, kc = idx & 31;
                phi_n[(kc * 2) * PHI_STR + c]     = __low2half(pre_phi[i]);
                phi_n[(kc * 2 + 1) * PHI_STR + c] = __high2half(pre_phi[i]);
            }
#pragma unroll
            for (int i = 0; i < 16; i++) {
                int idx = i * 128 + tid;
                int c2 = idx >> 4, kq = idx & 15;
                *(uint2*)(g_n + c2 * G_STR + kq * 4) = pre_g[i];
            }
        }
        __syncthreads();
    }

    l0 += __shfl_xor_sync(0xffffffffu, l0, 1, 4);
    l0 += __shfl_xor_sync(0xffffffffu, l0, 2, 4);
    l1 += __shfl_xor_sync(0xffffffffu, l1, 1, 4);
    l1 += __shfl_xor_sync(0xffffffffu, l1, 2, 4);
    float inv0 = 1.0f / l0;
    float inv1 = 1.0f / l1;

    float* dst0 = d_att + ((size_t)b * N_ + row0) * C2_ + qc * 2;
#pragma unroll
    for (int nt = 0; nt < 16; nt++) {
        *(float2*)(dst0 + nt * 8) =
            make_float2(O[nt][0] * inv0, O[nt][1] * inv0);
        *(float2*)(dst0 + 8 * C2_ + nt * 8) =
            make_float2(O[nt][2] * inv1, O[nt][3] * inv1);
    }
}

// ============================================================================
// Kernel 3: out = w_o @ att + b_o + x via fp16 mma, split-att. (exact R11)
// ============================================================================
#define WO_STR 136
#define AT_STR 40

__global__ void __launch_bounds__(256) out_tc_kernel(
    const float* __restrict__ wo, const float* __restrict__ bo,
    const float* __restrict__ x, float* __restrict__ out) {
    extern __shared__ __half smh[];
    __half* w_s = smh;                       // [32][WO_STR]
    __half* ah  = smh + 32 * WO_STR;         // [128][AT_STR]
    __half* al  = ah + 128 * AT_STR;         // [128][AT_STR]

    const int b  = blockIdx.y;
    const int Cbase = (blockIdx.x >> 5) * 32;
    const int N0    = (blockIdx.x & 31) * 128;
    const int tid  = threadIdx.x;
    const int wid  = tid >> 5, lane = tid & 31;
    const int m0   = (wid >> 2) * 16;
    const int n0w  = (wid & 3) * 32;
    const int qr = lane >> 2, qc = lane & 3;

#pragma unroll
    for (int i = 0; i < 16; i++) {
        int idx = i * 256 + tid;
        int r = idx >> 7, kk = idx & 127;
        w_s[r * WO_STR + kk] = __float2half_rn(wo[(Cbase + r) * C2_ + kk]);
    }

    float acc[4][4];
#pragma unroll
    for (int nt = 0; nt < 4; nt++)
#pragma unroll
        for (int j = 0; j < 4; j++) acc[nt][j] = 0.f;

    for (int kp = 0; kp < 4; kp++) {
        const int k0 = kp * 32;
        __syncthreads();
#pragma unroll
        for (int i = 0; i < 4; i++) {
            int idx = i * 256 + tid;
            int nn = idx >> 3, kk4 = idx & 7;
            float4 v = *(const float4*)(
                d_att + ((size_t)b * N_ + N0 + nn) * C2_ + k0 + kk4 * 4);
            __half2 h01 = __floats2half2_rn(v.x, v.y);
            __half2 h23 = __floats2half2_rn(v.z, v.w);
            __half2 l01 = __floats2half2_rn(v.x - __half2float(__low2half(h01)),
                                            v.y - __half2float(__high2half(h01)));
            __half2 l23 = __floats2half2_rn(v.z - __half2float(__low2half(h23)),
                                            v.w - __half2float(__high2half(h23)));
            *(__half2*)(ah + nn * AT_STR + kk4 * 4)     = h01;
            *(__half2*)(ah + nn * AT_STR + kk4 * 4 + 2) = h23;
            *(__half2*)(al + nn * AT_STR + kk4 * 4)     = l01;
            *(__half2*)(al + nn * AT_STR + kk4 * 4 + 2) = l23;
        }
        __syncthreads();

#pragma unroll
        for (int ks = 0; ks < 2; ks++) {
            const __half* wrow = w_s + (m0 + qr) * WO_STR + k0 + ks * 16 + 2 * qc;
            unsigned a0 = *(const unsigned*)wrow;
            unsigned a1 = *(const unsigned*)(wrow + 8 * WO_STR);
            unsigned a2 = *(const unsigned*)(wrow + 8);
            unsigned a3 = *(const unsigned*)(wrow + 8 * WO_STR + 8);
#pragma unroll
            for (int nt = 0; nt < 4; nt++) {
                const __half* bh = ah + (n0w + nt * 8 + qr) * AT_STR + ks * 16 + 2 * qc;
                const __half* bl = al + (n0w + nt * 8 + qr) * AT_STR + ks * 16 + 2 * qc;
                unsigned b0 = *(const unsigned*)bh;
                unsigned b1 = *(const unsigned*)(bh + 8);
                mma_f16(acc[nt][0], acc[nt][1], acc[nt][2], acc[nt][3],
                        a0, a1, a2, a3, b0, b1);
                unsigned c0 = *(const unsigned*)bl;
                unsigned c1 = *(const unsigned*)(bl + 8);
                mma_f16(acc[nt][0], acc[nt][1], acc[nt][2], acc[nt][3],
                        a0, a1, a2, a3, c0, c1);
            }
        }
    }

#pragma unroll
    for (int rr = 0; rr < 2; rr++) {
        int c = Cbase + m0 + qr + rr * 8;
        float bias = bo[c];
#pragma unroll
        for (int nt = 0; nt < 4; nt++) {
            int n = N0 + n0w + qc * 2 + nt * 8;
            size_t idx = ((size_t)b * C_ + c) * N_ + n;
            float2 xv = *(const float2*)(x + idx);
            *(float2*)(out + idx) = make_float2(
                acc[nt][rr * 2] + bias + xv.x,
                acc[nt][rr * 2 + 1] + bias + xv.y);
        }
    }
}

// ============================================================================
extern "C" void kernel_launch(void* const* d_in, const int* in_sizes, int n_in,
                              void* d_out, int out_size) {
    (void)in_sizes; (void)n_in; (void)out_size;
    const float* x  = (const float*)d_in[0];
    const float* wt = (const float*)d_in[1];
    const float* bt = (const float*)d_in[2];
    const float* wp = (const float*)d_in[3];
    const float* bp = (const float*)d_in[4];
    const float* wg = (const float*)d_in[5];
    const float* bg = (const float*)d_in[6];
    const float* wo = (const float*)d_in[7];
    const float* bo = (const float*)d_in[8];
    float* out = (float*)d_out;

    const int smem_proj  = (96 * 36 + 2 * 32 * 136) * 4;         // 48640
    const int smem_flash = 2 * (PHI_BUF + G_BUF) * 2;            // 47104
    const int smem_out   = (32 * WO_STR + 2 * 128 * AT_STR) * 2; // 29184

    cudaFuncSetAttribute(proj_tc_kernel,
                         cudaFuncAttributeMaxDynamicSharedMemorySize, smem_proj);
    cudaFuncSetAttribute(flash_tc_kernel,
                         cudaFuncAttributeMaxDynamicSharedMemorySize, smem_flash);
    cudaFuncSetAttribute(out_tc_kernel,
                         cudaFuncAttributeMaxDynamicSharedMemorySize, smem_out);

    proj_tc_kernel<<<dim3(64, B_), 256, smem_proj>>>(x, wt, bt, wp, bp, wg, bg);
    flash_tc_kernel<<<dim3(N_ / 64, B_), 128, smem_flash>>>();
    out_tc_kernel<<<dim3(256, B_), 256, smem_out>>>(wo, bo, x, out);
}

// round 15
// speedup vs baseline: 1.3210x; 1.0886x over previous
#include <cuda_runtime.h>
#include <cuda_fp16.h>

// NonLocalAttention: B=4, C=256, H=W=64 -> N=4096, C8=32, C2=128
//   proj_tc_kernel : projections (tf32 mma, split-x), 96 outs/CTA (exact R12)
//   flash_tc_kernel: fp16 flash attention, double-buffered, 128-query CTA
//   out_tc_kernel  : w_o @ att + b_o + x (fp16 mma, split-att) (exact R11)

#define B_ 4
#define C_ 256
#define N_ 4096
#define C8_ 32
#define C2_ 128

__device__ __half d_theta[(size_t)B_ * C8_ * N_];   // theta * log2e
__device__ __half d_phi[(size_t)B_ * C8_ * N_];
__device__ __half d_g[(size_t)B_ * C2_ * N_];       // [b][c2][n]
__device__ float  d_att[(size_t)B_ * N_ * C2_];

// ---- intrinsics ----
__device__ __forceinline__ unsigned cvt_tf32(float x) {
    unsigned r;
    asm("cvt.rna.tf32.f32 %0, %1;" : "=r"(r) : "f"(x));
    return r;
}
__device__ __forceinline__ float cvt_tf32f(float x) {
    return __uint_as_float(cvt_tf32(x));
}
__device__ __forceinline__ float ex2f(float x) {
    float r;
    asm("ex2.approx.f32 %0, %1;" : "=f"(r) : "f"(x));
    return r;
}
__device__ __forceinline__ void mma_tf32(
    float& c0, float& c1, float& c2, float& c3,
    unsigned a0, unsigned a1, unsigned a2, unsigned a3,
    unsigned b0, unsigned b1) {
    asm("mma.sync.aligned.m16n8k8.row.col.f32.tf32.tf32.f32 "
        "{%0,%1,%2,%3}, {%4,%5,%6,%7}, {%8,%9}, {%0,%1,%2,%3};"
        : "+f"(c0), "+f"(c1), "+f"(c2), "+f"(c3)
        : "r"(a0), "r"(a1), "r"(a2), "r"(a3), "r"(b0), "r"(b1));
}
__device__ __forceinline__ void mma_f16(
    float& c0, float& c1, float& c2, float& c3,
    unsigned a0, unsigned a1, unsigned a2, unsigned a3,
    unsigned b0, unsigned b1) {
    asm("mma.sync.aligned.m16n8k16.row.col.f32.f16.f16.f32 "
        "{%0,%1,%2,%3}, {%4,%5,%6,%7}, {%8,%9}, {%0,%1,%2,%3};"
        : "+f"(c0), "+f"(c1), "+f"(c2), "+f"(c3)
        : "r"(a0), "r"(a1), "r"(a2), "r"(a3), "r"(b0), "r"(b1));
}
__device__ __forceinline__ unsigned packh2(float lo, float hi) {
    __half2 h = __floats2half2_rn(lo, hi);
    return *(unsigned*)&h;
}

// ============================================================================
// Kernel 1: projections via tf32 mma, split-x. 96 outputs per CTA. (exact R12)
// ============================================================================
__global__ void __launch_bounds__(256) proj_tc_kernel(
    const float* __restrict__ x,
    const float* __restrict__ wt, const float* __restrict__ bt,
    const float* __restrict__ wp, const float* __restrict__ bp,
    const float* __restrict__ wg, const float* __restrict__ bg) {
    extern __shared__ float sm[];
    float* ws = sm;                 // [96][36]
    float* xh = sm + 96 * 36;       // [32][136]
    float* xl = xh + 32 * 136;      // [32][136]

    const int b  = blockIdx.y;
    const int Mbase = (blockIdx.x >> 5) * 96;
    const int N0    = (blockIdx.x & 31) * 128;
    const int tid  = threadIdx.x;
    const int wid  = tid >> 5, lane = tid & 31;
    const int m0   = (wid >> 2) * 16;
    const int n0w  = (wid & 3) * 32;
    const int qr = lane >> 2, qc = lane & 3;

    float acc[3][4][4];
#pragma unroll
    for (int mt = 0; mt < 3; mt++)
#pragma unroll
        for (int nt = 0; nt < 4; nt++)
#pragma unroll
            for (int j = 0; j < 4; j++) acc[mt][nt][j] = 0.f;

    for (int kp = 0; kp < 8; kp++) {
        const int k0 = kp * 32;
        __syncthreads();
#pragma unroll
        for (int i = 0; i < 12; i++) {
            int idx = i * 256 + tid;
            int r = idx >> 5, kk = idx & 31;
            int o = Mbase + r;
            const float* src = (o < 32) ? wt + o * C_
                             : (o < 64) ? wp + (o - 32) * C_
                                        : wg + (o - 64) * C_;
            ws[r * 36 + kk] = cvt_tf32f(src[k0 + kk]);
        }
#pragma unroll
        for (int i = 0; i < 4; i++) {
            int idx = i * 256 + tid;
            int cc = idx >> 5, nn4 = idx & 31;
            float4 v = *(const float4*)(
                x + ((size_t)(b * C_ + k0 + cc)) * N_ + N0 + nn4 * 4);
            float4 h, l;
            h.x = cvt_tf32f(v.x); l.x = v.x - h.x;
            h.y = cvt_tf32f(v.y); l.y = v.y - h.y;
            h.z = cvt_tf32f(v.z); l.z = v.z - h.z;
            h.w = cvt_tf32f(v.w); l.w = v.w - h.w;
            *(float4*)(xh + cc * 136 + nn4 * 4) = h;
            *(float4*)(xl + cc * 136 + nn4 * 4) = l;
        }
        __syncthreads();

#pragma unroll
        for (int ks = 0; ks < 4; ks++) {
            const float* bh = xh + (ks * 8 + qc) * 136 + n0w + qr;
            const float* bl = xl + (ks * 8 + qc) * 136 + n0w + qr;
            unsigned bh0[4], bh1[4], bl0[4], bl1[4];
#pragma unroll
            for (int nt = 0; nt < 4; nt++) {
                bh0[nt] = __float_as_uint(bh[nt * 8]);
                bh1[nt] = __float_as_uint(bh[4 * 136 + nt * 8]);
                bl0[nt] = __float_as_uint(bl[nt * 8]);
                bl1[nt] = __float_as_uint(bl[4 * 136 + nt * 8]);
            }
#pragma unroll
            for (int mt = 0; mt < 3; mt++) {
                const float* wrow = ws + (mt * 32 + m0 + qr) * 36 + ks * 8 + qc;
                unsigned a0 = __float_as_uint(wrow[0]);
                unsigned a1 = __float_as_uint(wrow[8 * 36]);
                unsigned a2 = __float_as_uint(wrow[4]);
                unsigned a3 = __float_as_uint(wrow[8 * 36 + 4]);
#pragma unroll
                for (int nt = 0; nt < 4; nt++) {
                    mma_tf32(acc[mt][nt][0], acc[mt][nt][1],
                             acc[mt][nt][2], acc[mt][nt][3],
                             a0, a1, a2, a3, bh0[nt], bh1[nt]);
                    mma_tf32(acc[mt][nt][0], acc[mt][nt][1],
                             acc[mt][nt][2], acc[mt][nt][3],
                             a0, a1, a2, a3, bl0[nt], bl1[nt]);
                }
            }
        }
    }

    const float LOG2E = 1.4426950408889634f;
#pragma unroll
    for (int mt = 0; mt < 3; mt++) {
#pragma unroll
        for (int rr = 0; rr < 2; rr++) {
            int o = Mbase + mt * 32 + m0 + qr + rr * 8;
            if (o < 32) {
                float bias = bt[o];
                __half2* dst = (__half2*)(d_theta + ((size_t)b * C8_ + o) * N_ +
                                          N0 + n0w + qc * 2);
#pragma unroll
                for (int nt = 0; nt < 4; nt++)
                    dst[nt * 4] = __floats2half2_rn(
                        (acc[mt][nt][rr * 2] + bias) * LOG2E,
                        (acc[mt][nt][rr * 2 + 1] + bias) * LOG2E);
            } else if (o < 64) {
                float bias = bp[o - 32];
                __half2* dst = (__half2*)(d_phi + ((size_t)b * C8_ + (o - 32)) * N_ +
                                          N0 + n0w + qc * 2);
#pragma unroll
                for (int nt = 0; nt < 4; nt++)
                    dst[nt * 4] = __floats2half2_rn(
                        acc[mt][nt][rr * 2] + bias, acc[mt][nt][rr * 2 + 1] + bias);
            } else {
                float bias = bg[o - 64];
                __half2* dst = (__half2*)(d_g + ((size_t)b * C2_ + (o - 64)) * N_ +
                                          N0 + n0w + qc * 2);
#pragma unroll
                for (int nt = 0; nt < 4; nt++)
                    dst[nt * 4] = __floats2half2_rn(
                        acc[mt][nt][rr * 2] + bias, acc[mt][nt][rr * 2 + 1] + bias);
            }
        }
    }
}

// ============================================================================
// Kernel 2: fp16 flash attention, double-buffered, 128-query CTA (8 warps).
// ============================================================================
#define PHI_STR 40
#define G_STR   72
#define PHI_BUF (64 * PHI_STR)
#define G_BUF   (128 * G_STR)
#define NTILES  (N_ / 64)

__global__ void __launch_bounds__(256) flash_tc_kernel() {
    extern __shared__ __half smh[];
    // layout: phi[0], phi[1], g[0], g[1]
    __half* g_base = smh + 2 * PHI_BUF;

    const int b   = blockIdx.y;
    const int q0  = blockIdx.x * 128;
    const int tid = threadIdx.x;
    const int w    = tid >> 5;            // 8 warps, 16 q rows each
    const int lane = tid & 31;
    const int qr = lane >> 2;
    const int qc = lane & 3;
    const int row0 = q0 + w * 16 + qr;

    unsigned at[2][4];
    {
        const __half* tp = d_theta + (size_t)b * C8_ * N_;
#pragma unroll
        for (int ks = 0; ks < 2; ks++) {
            int c = ks * 16 + 2 * qc;
            at[ks][0] = packh2(__half2float(tp[(size_t)c * N_ + row0]),
                               __half2float(tp[(size_t)(c + 1) * N_ + row0]));
            at[ks][1] = packh2(__half2float(tp[(size_t)c * N_ + row0 + 8]),
                               __half2float(tp[(size_t)(c + 1) * N_ + row0 + 8]));
            at[ks][2] = packh2(__half2float(tp[(size_t)(c + 8) * N_ + row0]),
                               __half2float(tp[(size_t)(c + 9) * N_ + row0]));
            at[ks][3] = packh2(__half2float(tp[(size_t)(c + 8) * N_ + row0 + 8]),
                               __half2float(tp[(size_t)(c + 9) * N_ + row0 + 8]));
        }
    }

    float O[16][4];
#pragma unroll
    for (int nt = 0; nt < 16; nt++)
#pragma unroll
        for (int j = 0; j < 4; j++) O[nt][j] = 0.f;
    float m0 = -1e30f, m1 = -1e30f, l0 = 0.f, l1 = 0.f;

    // ---- prologue: stage tile 0 into buffer 0 (256 threads) ----
    {
        __half* phi_s = smh;
        __half* g_s   = g_base;
#pragma unroll
        for (int i = 0; i < 4; i++) {
            int idx = i * 256 + tid;            // 0..1023
            int c = idx >> 5, kc = idx & 31;
            __half2 v = *(const __half2*)(
                d_phi + ((size_t)b * C8_ + c) * N_ + kc * 2);
            phi_s[(kc * 2) * PHI_STR + c]     = __low2half(v);
            phi_s[(kc * 2 + 1) * PHI_STR + c] = __high2half(v);
        }
#pragma unroll
        for (int i = 0; i < 8; i++) {
            int idx = i * 256 + tid;            // 0..2047
            int c2 = idx >> 4, kq = idx & 15;
            uint2 v = *(const uint2*)(
                d_g + ((size_t)b * C2_ + c2) * N_ + kq * 4);
            *(uint2*)(g_s + c2 * G_STR + kq * 4) = v;
        }
    }
    __syncthreads();

    for (int it = 0; it < NTILES; it++) {
        const int cur = it & 1;
        __half* phi_s = smh + cur * PHI_BUF;
        __half* g_s   = g_base + cur * G_BUF;
        __half* phi_n = smh + (1 - cur) * PHI_BUF;
        __half* g_n   = g_base + (1 - cur) * G_BUF;

        // ---- prefetch LDGs for tile it+1 (into registers) ----
        __half2 pre_phi[4];
        uint2   pre_g[8];
        const bool has_next = (it < NTILES - 1);
        if (has_next) {
            const int kt2 = (it + 1) * 64;
#pragma unroll
            for (int i = 0; i < 4; i++) {
                int idx = i * 256 + tid;
                int c = idx >> 5, kc = idx & 31;
                pre_phi[i] = *(const __half2*)(
                    d_phi + ((size_t)b * C8_ + c) * N_ + kt2 + kc * 2);
            }
#pragma unroll
            for (int i = 0; i < 8; i++) {
                int idx = i * 256 + tid;
                int c2 = idx >> 4, kq = idx & 15;
                pre_g[i] = *(const uint2*)(
                    d_g + ((size_t)b * C2_ + c2) * N_ + kt2 + kq * 4);
            }
        }

        // ---- GEMM1: S = theta @ phi^T ----
        float s[8][4];
#pragma unroll
        for (int nt = 0; nt < 8; nt++)
#pragma unroll
            for (int j = 0; j < 4; j++) s[nt][j] = 0.f;

#pragma unroll
        for (int ks = 0; ks < 2; ks++) {
#pragma unroll
            for (int nt = 0; nt < 8; nt++) {
                const __half* pb = phi_s + (nt * 8 + qr) * PHI_STR + ks * 16 + 2 * qc;
                unsigned b0 = *(const unsigned*)pb;
                unsigned b1 = *(const unsigned*)(pb + 8);
                mma_f16(s[nt][0], s[nt][1], s[nt][2], s[nt][3],
                        at[ks][0], at[ks][1], at[ks][2], at[ks][3], b0, b1);
            }
        }

        // ---- online-max softmax ----
        float rm0 = -1e30f, rm1 = -1e30f;
#pragma unroll
        for (int nt = 0; nt < 8; nt++) {
            rm0 = fmaxf(rm0, fmaxf(s[nt][0], s[nt][1]));
            rm1 = fmaxf(rm1, fmaxf(s[nt][2], s[nt][3]));
        }
        rm0 = fmaxf(rm0, __shfl_xor_sync(0xffffffffu, rm0, 1, 4));
        rm0 = fmaxf(rm0, __shfl_xor_sync(0xffffffffu, rm0, 2, 4));
        rm1 = fmaxf(rm1, __shfl_xor_sync(0xffffffffu, rm1, 1, 4));
        rm1 = fmaxf(rm1, __shfl_xor_sync(0xffffffffu, rm1, 2, 4));
        float mn0 = fmaxf(m0, rm0), mn1 = fmaxf(m1, rm1);
        float cr0 = ex2f(m0 - mn0), cr1 = ex2f(m1 - mn1);
        m0 = mn0; m1 = mn1;
#pragma unroll
        for (int nt = 0; nt < 16; nt++) {
            O[nt][0] *= cr0; O[nt][1] *= cr0;
            O[nt][2] *= cr1; O[nt][3] *= cr1;
        }

        unsigned pk[8][2];
        float rs0 = 0.f, rs1 = 0.f;
#pragma unroll
        for (int nt = 0; nt < 8; nt++) {
            float e0 = ex2f(s[nt][0] - mn0);
            float e1 = ex2f(s[nt][1] - mn0);
            float e2 = ex2f(s[nt][2] - mn1);
            float e3 = ex2f(s[nt][3] - mn1);
            rs0 += e0 + e1; rs1 += e2 + e3;
            pk[nt][0] = packh2(e0, e1);
            pk[nt][1] = packh2(e2, e3);
        }
        l0 = l0 * cr0 + rs0;
        l1 = l1 * cr1 + rs1;

        // ---- GEMM2: O += P @ g ----
#pragma unroll
        for (int kb = 0; kb < 4; kb++) {
            unsigned a0 = pk[2 * kb][0];
            unsigned a1 = pk[2 * kb][1];
            unsigned a2 = pk[2 * kb + 1][0];
            unsigned a3 = pk[2 * kb + 1][1];
#pragma unroll
            for (int nt = 0; nt < 16; nt++) {
                const __half* gb = g_s + (nt * 8 + qr) * G_STR + kb * 16 + 2 * qc;
                unsigned b0 = *(const unsigned*)gb;
                unsigned b1 = *(const unsigned*)(gb + 8);
                mma_f16(O[nt][0], O[nt][1], O[nt][2], O[nt][3],
                        a0, a1, a2, a3, b0, b1);
            }
        }

        // ---- STS prefetched tile into the other buffer ----
        if (has_next) {
#pragma unroll
            for (int i = 0; i < 4; i++) {
                int idx = i * 256 + tid;
                int c = idx >> 5, kc = idx & 31;
                phi_n[(kc * 2) * PHI_STR + c]     = __low2half(pre_phi[i]);
                phi_n[(kc * 2 + 1) * PHI_STR + c] = __high2half(pre_phi[i]);
            }
#pragma unroll
            for (int i = 0; i < 8; i++) {
                int idx = i * 256 + tid;
                int c2 = idx >> 4, kq = idx & 15;
                *(uint2*)(g_n + c2 * G_STR + kq * 4) = pre_g[i];
            }
        }
        __syncthreads();
    }

    l0 += __shfl_xor_sync(0xffffffffu, l0, 1, 4);
    l0 += __shfl_xor_sync(0xffffffffu, l0, 2, 4);
    l1 += __shfl_xor_sync(0xffffffffu, l1, 1, 4);
    l1 += __shfl_xor_sync(0xffffffffu, l1, 2, 4);
    float inv0 = 1.0f / l0;
    float inv1 = 1.0f / l1;

    float* dst0 = d_att + ((size_t)b * N_ + row0) * C2_ + qc * 2;
#pragma unroll
    for (int nt = 0; nt < 16; nt++) {
        *(float2*)(dst0 + nt * 8) =
            make_float2(O[nt][0] * inv0, O[nt][1] * inv0);
        *(float2*)(dst0 + 8 * C2_ + nt * 8) =
            make_float2(O[nt][2] * inv1, O[nt][3] * inv1);
    }
}

// ============================================================================
// Kernel 3: out = w_o @ att + b_o + x via fp16 mma, split-att. (exact R11)
// ============================================================================
#define WO_STR 136
#define AT_STR 40

__global__ void __launch_bounds__(256) out_tc_kernel(
    const float* __restrict__ wo, const float* __restrict__ bo,
    const float* __restrict__ x, float* __restrict__ out) {
    extern __shared__ __half smh[];
    __half* w_s = smh;                       // [32][WO_STR]
    __half* ah  = smh + 32 * WO_STR;         // [128][AT_STR]
    __half* al  = ah + 128 * AT_STR;         // [128][AT_STR]

    const int b  = blockIdx.y;
    const int Cbase = (blockIdx.x >> 5) * 32;
    const int N0    = (blockIdx.x & 31) * 128;
    const int tid  = threadIdx.x;
    const int wid  = tid >> 5, lane = tid & 31;
    const int m0   = (wid >> 2) * 16;
    const int n0w  = (wid & 3) * 32;
    const int qr = lane >> 2, qc = lane & 3;

#pragma unroll
    for (int i = 0; i < 16; i++) {
        int idx = i * 256 + tid;
        int r = idx >> 7, kk = idx & 127;
        w_s[r * WO_STR + kk] = __float2half_rn(wo[(Cbase + r) * C2_ + kk]);
    }

    float acc[4][4];
#pragma unroll
    for (int nt = 0; nt < 4; nt++)
#pragma unroll
        for (int j = 0; j < 4; j++) acc[nt][j] = 0.f;

    for (int kp = 0; kp < 4; kp++) {
        const int k0 = kp * 32;
        __syncthreads();
#pragma unroll
        for (int i = 0; i < 4; i++) {
            int idx = i * 256 + tid;
            int nn = idx >> 3, kk4 = idx & 7;
            float4 v = *(const float4*)(
                d_att + ((size_t)b * N_ + N0 + nn) * C2_ + k0 + kk4 * 4);
            __half2 h01 = __floats2half2_rn(v.x, v.y);
            __half2 h23 = __floats2half2_rn(v.z, v.w);
            __half2 l01 = __floats2half2_rn(v.x - __half2float(__low2half(h01)),
                                            v.y - __half2float(__high2half(h01)));
            __half2 l23 = __floats2half2_rn(v.z - __half2float(__low2half(h23)),
                                            v.w - __half2float(__high2half(h23)));
            *(__half2*)(ah + nn * AT_STR + kk4 * 4)     = h01;
            *(__half2*)(ah + nn * AT_STR + kk4 * 4 + 2) = h23;
            *(__half2*)(al + nn * AT_STR + kk4 * 4)     = l01;
            *(__half2*)(al + nn * AT_STR + kk4 * 4 + 2) = l23;
        }
        __syncthreads();

#pragma unroll
        for (int ks = 0; ks < 2; ks++) {
            const __half* wrow = w_s + (m0 + qr) * WO_STR + k0 + ks * 16 + 2 * qc;
            unsigned a0 = *(const unsigned*)wrow;
            unsigned a1 = *(const unsigned*)(wrow + 8 * WO_STR);
            unsigned a2 = *(const unsigned*)(wrow + 8);
            unsigned a3 = *(const unsigned*)(wrow + 8 * WO_STR + 8);
#pragma unroll
            for (int nt = 0; nt < 4; nt++) {
                const __half* bh = ah + (n0w + nt * 8 + qr) * AT_STR + ks * 16 + 2 * qc;
                const __half* bl = al + (n0w + nt * 8 + qr) * AT_STR + ks * 16 + 2 * qc;
                unsigned b0 = *(const unsigned*)bh;
                unsigned b1 = *(const unsigned*)(bh + 8);
                mma_f16(acc[nt][0], acc[nt][1], acc[nt][2], acc[nt][3],
                        a0, a1, a2, a3, b0, b1);
                unsigned c0 = *(const unsigned*)bl;
                unsigned c1 = *(const unsigned*)(bl + 8);
                mma_f16(acc[nt][0], acc[nt][1], acc[nt][2], acc[nt][3],
                        a0, a1, a2, a3, c0, c1);
            }
        }
    }

#pragma unroll
    for (int rr = 0; rr < 2; rr++) {
        int c = Cbase + m0 + qr + rr * 8;
        float bias = bo[c];
#pragma unroll
        for (int nt = 0; nt < 4; nt++) {
            int n = N0 + n0w + qc * 2 + nt * 8;
            size_t idx = ((size_t)b * C_ + c) * N_ + n;
            float2 xv = *(const float2*)(x + idx);
            *(float2*)(out + idx) = make_float2(
                acc[nt][rr * 2] + bias + xv.x,
                acc[nt][rr * 2 + 1] + bias + xv.y);
        }
    }
}

// ============================================================================
extern "C" void kernel_launch(void* const* d_in, const int* in_sizes, int n_in,
                              void* d_out, int out_size) {
    (void)in_sizes; (void)n_in; (void)out_size;
    const float* x  = (const float*)d_in[0];
    const float* wt = (const float*)d_in[1];
    const float* bt = (const float*)d_in[2];
    const float* wp = (const float*)d_in[3];
    const float* bp = (const float*)d_in[4];
    const float* wg = (const float*)d_in[5];
    const float* bg = (const float*)d_in[6];
    const float* wo = (const float*)d_in[7];
    const float* bo = (const float*)d_in[8];
    float* out = (float*)d_out;

    const int smem_proj  = (96 * 36 + 2 * 32 * 136) * 4;         // 48640
    const int smem_flash = 2 * (PHI_BUF + G_BUF) * 2;            // 47104
    const int smem_out   = (32 * WO_STR + 2 * 128 * AT_STR) * 2; // 29184

    cudaFuncSetAttribute(proj_tc_kernel,
                         cudaFuncAttributeMaxDynamicSharedMemorySize, smem_proj);
    cudaFuncSetAttribute(flash_tc_kernel,
                         cudaFuncAttributeMaxDynamicSharedMemorySize, smem_flash);
    cudaFuncSetAttribute(out_tc_kernel,
                         cudaFuncAttributeMaxDynamicSharedMemorySize, smem_out);

    proj_tc_kernel<<<dim3(64, B_), 256, smem_proj>>>(x, wt, bt, wp, bp, wg, bg);
    flash_tc_kernel<<<dim3(N_ / 128, B_), 256, smem_flash>>>();
    out_tc_kernel<<<dim3(256, B_), 256, smem_out>>>(wo, bo, x, out);
}

// round 16
// speedup vs baseline: 1.3564x; 1.0268x over previous
#include <cuda_runtime.h>
#include <cuda_fp16.h>

// NonLocalAttention: B=4, C=256, H=W=64 -> N=4096, C8=32, C2=128
//   proj_tc_kernel : projections (tf32 mma, split-x), 96 outs/CTA (exact R12)
//   flash_tc_kernel: fp16 flash, double-buffered, 128-query CTA (exact R15)
//   out_tc_kernel  : w_o @ att + b_o + x (fp16 mma, split-att), 128 ch/CTA
//                    (4 M-groups merged: att staging + h/l split amortized)

#define B_ 4
#define C_ 256
#define N_ 4096
#define C8_ 32
#define C2_ 128

__device__ __half d_theta[(size_t)B_ * C8_ * N_];   // theta * log2e
__device__ __half d_phi[(size_t)B_ * C8_ * N_];
__device__ __half d_g[(size_t)B_ * C2_ * N_];       // [b][c2][n]
__device__ float  d_att[(size_t)B_ * N_ * C2_];

// ---- intrinsics ----
__device__ __forceinline__ unsigned cvt_tf32(float x) {
    unsigned r;
    asm("cvt.rna.tf32.f32 %0, %1;" : "=r"(r) : "f"(x));
    return r;
}
__device__ __forceinline__ float cvt_tf32f(float x) {
    return __uint_as_float(cvt_tf32(x));
}
__device__ __forceinline__ float ex2f(float x) {
    float r;
    asm("ex2.approx.f32 %0, %1;" : "=f"(r) : "f"(x));
    return r;
}
__device__ __forceinline__ void mma_tf32(
    float& c0, float& c1, float& c2, float& c3,
    unsigned a0, unsigned a1, unsigned a2, unsigned a3,
    unsigned b0, unsigned b1) {
    asm("mma.sync.aligned.m16n8k8.row.col.f32.tf32.tf32.f32 "
        "{%0,%1,%2,%3}, {%4,%5,%6,%7}, {%8,%9}, {%0,%1,%2,%3};"
        : "+f"(c0), "+f"(c1), "+f"(c2), "+f"(c3)
        : "r"(a0), "r"(a1), "r"(a2), "r"(a3), "r"(b0), "r"(b1));
}
__device__ __forceinline__ void mma_f16(
    float& c0, float& c1, float& c2, float& c3,
    unsigned a0, unsigned a1, unsigned a2, unsigned a3,
    unsigned b0, unsigned b1) {
    asm("mma.sync.aligned.m16n8k16.row.col.f32.f16.f16.f32 "
        "{%0,%1,%2,%3}, {%4,%5,%6,%7}, {%8,%9}, {%0,%1,%2,%3};"
        : "+f"(c0), "+f"(c1), "+f"(c2), "+f"(c3)
        : "r"(a0), "r"(a1), "r"(a2), "r"(a3), "r"(b0), "r"(b1));
}
__device__ __forceinline__ unsigned packh2(float lo, float hi) {
    __half2 h = __floats2half2_rn(lo, hi);
    return *(unsigned*)&h;
}

// ============================================================================
// Kernel 1: projections via tf32 mma, split-x. 96 outputs per CTA. (exact R12)
// ============================================================================
__global__ void __launch_bounds__(256) proj_tc_kernel(
    const float* __restrict__ x,
    const float* __restrict__ wt, const float* __restrict__ bt,
    const float* __restrict__ wp, const float* __restrict__ bp,
    const float* __restrict__ wg, const float* __restrict__ bg) {
    extern __shared__ float sm[];
    float* ws = sm;                 // [96][36]
    float* xh = sm + 96 * 36;       // [32][136]
    float* xl = xh + 32 * 136;      // [32][136]

    const int b  = blockIdx.y;
    const int Mbase = (blockIdx.x >> 5) * 96;
    const int N0    = (blockIdx.x & 31) * 128;
    const int tid  = threadIdx.x;
    const int wid  = tid >> 5, lane = tid & 31;
    const int m0   = (wid >> 2) * 16;
    const int n0w  = (wid & 3) * 32;
    const int qr = lane >> 2, qc = lane & 3;

    float acc[3][4][4];
#pragma unroll
    for (int mt = 0; mt < 3; mt++)
#pragma unroll
        for (int nt = 0; nt < 4; nt++)
#pragma unroll
            for (int j = 0; j < 4; j++) acc[mt][nt][j] = 0.f;

    for (int kp = 0; kp < 8; kp++) {
        const int k0 = kp * 32;
        __syncthreads();
#pragma unroll
        for (int i = 0; i < 12; i++) {
            int idx = i * 256 + tid;
            int r = idx >> 5, kk = idx & 31;
            int o = Mbase + r;
            const float* src = (o < 32) ? wt + o * C_
                             : (o < 64) ? wp + (o - 32) * C_
                                        : wg + (o - 64) * C_;
            ws[r * 36 + kk] = cvt_tf32f(src[k0 + kk]);
        }
#pragma unroll
        for (int i = 0; i < 4; i++) {
            int idx = i * 256 + tid;
            int cc = idx >> 5, nn4 = idx & 31;
            float4 v = *(const float4*)(
                x + ((size_t)(b * C_ + k0 + cc)) * N_ + N0 + nn4 * 4);
            float4 h, l;
            h.x = cvt_tf32f(v.x); l.x = v.x - h.x;
            h.y = cvt_tf32f(v.y); l.y = v.y - h.y;
            h.z = cvt_tf32f(v.z); l.z = v.z - h.z;
            h.w = cvt_tf32f(v.w); l.w = v.w - h.w;
            *(float4*)(xh + cc * 136 + nn4 * 4) = h;
            *(float4*)(xl + cc * 136 + nn4 * 4) = l;
        }
        __syncthreads();

#pragma unroll
        for (int ks = 0; ks < 4; ks++) {
            const float* bh = xh + (ks * 8 + qc) * 136 + n0w + qr;
            const float* bl = xl + (ks * 8 + qc) * 136 + n0w + qr;
            unsigned bh0[4], bh1[4], bl0[4], bl1[4];
#pragma unroll
            for (int nt = 0; nt < 4; nt++) {
                bh0[nt] = __float_as_uint(bh[nt * 8]);
                bh1[nt] = __float_as_uint(bh[4 * 136 + nt * 8]);
                bl0[nt] = __float_as_uint(bl[nt * 8]);
                bl1[nt] = __float_as_uint(bl[4 * 136 + nt * 8]);
            }
#pragma unroll
            for (int mt = 0; mt < 3; mt++) {
                const float* wrow = ws + (mt * 32 + m0 + qr) * 36 + ks * 8 + qc;
                unsigned a0 = __float_as_uint(wrow[0]);
                unsigned a1 = __float_as_uint(wrow[8 * 36]);
                unsigned a2 = __float_as_uint(wrow[4]);
                unsigned a3 = __float_as_uint(wrow[8 * 36 + 4]);
#pragma unroll
                for (int nt = 0; nt < 4; nt++) {
                    mma_tf32(acc[mt][nt][0], acc[mt][nt][1],
                             acc[mt][nt][2], acc[mt][nt][3],
                             a0, a1, a2, a3, bh0[nt], bh1[nt]);
                    mma_tf32(acc[mt][nt][0], acc[mt][nt][1],
                             acc[mt][nt][2], acc[mt][nt][3],
                             a0, a1, a2, a3, bl0[nt], bl1[nt]);
                }
            }
        }
    }

    const float LOG2E = 1.4426950408889634f;
#pragma unroll
    for (int mt = 0; mt < 3; mt++) {
#pragma unroll
        for (int rr = 0; rr < 2; rr++) {
            int o = Mbase + mt * 32 + m0 + qr + rr * 8;
            if (o < 32) {
                float bias = bt[o];
                __half2* dst = (__half2*)(d_theta + ((size_t)b * C8_ + o) * N_ +
                                          N0 + n0w + qc * 2);
#pragma unroll
                for (int nt = 0; nt < 4; nt++)
                    dst[nt * 4] = __floats2half2_rn(
                        (acc[mt][nt][rr * 2] + bias) * LOG2E,
                        (acc[mt][nt][rr * 2 + 1] + bias) * LOG2E);
            } else if (o < 64) {
                float bias = bp[o - 32];
                __half2* dst = (__half2*)(d_phi + ((size_t)b * C8_ + (o - 32)) * N_ +
                                          N0 + n0w + qc * 2);
#pragma unroll
                for (int nt = 0; nt < 4; nt++)
                    dst[nt * 4] = __floats2half2_rn(
                        acc[mt][nt][rr * 2] + bias, acc[mt][nt][rr * 2 + 1] + bias);
            } else {
                float bias = bg[o - 64];
                __half2* dst = (__half2*)(d_g + ((size_t)b * C2_ + (o - 64)) * N_ +
                                          N0 + n0w + qc * 2);
#pragma unroll
                for (int nt = 0; nt < 4; nt++)
                    dst[nt * 4] = __floats2half2_rn(
                        acc[mt][nt][rr * 2] + bias, acc[mt][nt][rr * 2 + 1] + bias);
            }
        }
    }
}

// ============================================================================
// Kernel 2: fp16 flash attention, double-buffered, 128-query CTA. (exact R15)
// ============================================================================
#define PHI_STR 40
#define G_STR   72
#define PHI_BUF (64 * PHI_STR)
#define G_BUF   (128 * G_STR)
#define NTILES  (N_ / 64)

__global__ void __launch_bounds__(256) flash_tc_kernel() {
    extern __shared__ __half smh[];
    __half* g_base = smh + 2 * PHI_BUF;

    const int b   = blockIdx.y;
    const int q0  = blockIdx.x * 128;
    const int tid = threadIdx.x;
    const int w    = tid >> 5;
    const int lane = tid & 31;
    const int qr = lane >> 2;
    const int qc = lane & 3;
    const int row0 = q0 + w * 16 + qr;

    unsigned at[2][4];
    {
        const __half* tp = d_theta + (size_t)b * C8_ * N_;
#pragma unroll
        for (int ks = 0; ks < 2; ks++) {
            int c = ks * 16 + 2 * qc;
            at[ks][0] = packh2(__half2float(tp[(size_t)c * N_ + row0]),
                               __half2float(tp[(size_t)(c + 1) * N_ + row0]));
            at[ks][1] = packh2(__half2float(tp[(size_t)c * N_ + row0 + 8]),
                               __half2float(tp[(size_t)(c + 1) * N_ + row0 + 8]));
            at[ks][2] = packh2(__half2float(tp[(size_t)(c + 8) * N_ + row0]),
                               __half2float(tp[(size_t)(c + 9) * N_ + row0]));
            at[ks][3] = packh2(__half2float(tp[(size_t)(c + 8) * N_ + row0 + 8]),
                               __half2float(tp[(size_t)(c + 9) * N_ + row0 + 8]));
        }
    }

    float O[16][4];
#pragma unroll
    for (int nt = 0; nt < 16; nt++)
#pragma unroll
        for (int j = 0; j < 4; j++) O[nt][j] = 0.f;
    float m0 = -1e30f, m1 = -1e30f, l0 = 0.f, l1 = 0.f;

    {
        __half* phi_s = smh;
        __half* g_s   = g_base;
#pragma unroll
        for (int i = 0; i < 4; i++) {
            int idx = i * 256 + tid;
            int c = idx >> 5, kc = idx & 31;
            __half2 v = *(const __half2*)(
                d_phi + ((size_t)b * C8_ + c) * N_ + kc * 2);
            phi_s[(kc * 2) * PHI_STR + c]     = __low2half(v);
            phi_s[(kc * 2 + 1) * PHI_STR + c] = __high2half(v);
        }
#pragma unroll
        for (int i = 0; i < 8; i++) {
            int idx = i * 256 + tid;
            int c2 = idx >> 4, kq = idx & 15;
            uint2 v = *(const uint2*)(
                d_g + ((size_t)b * C2_ + c2) * N_ + kq * 4);
            *(uint2*)(g_s + c2 * G_STR + kq * 4) = v;
        }
    }
    __syncthreads();

    for (int it = 0; it < NTILES; it++) {
        const int cur = it & 1;
        __half* phi_s = smh + cur * PHI_BUF;
        __half* g_s   = g_base + cur * G_BUF;
        __half* phi_n = smh + (1 - cur) * PHI_BUF;
        __half* g_n   = g_base + (1 - cur) * G_BUF;

        __half2 pre_phi[4];
        uint2   pre_g[8];
        const bool has_next = (it < NTILES - 1);
        if (has_next) {
            const int kt2 = (it + 1) * 64;
#pragma unroll
            for (int i = 0; i < 4; i++) {
                int idx = i * 256 + tid;
                int c = idx >> 5, kc = idx & 31;
                pre_phi[i] = *(const __half2*)(
                    d_phi + ((size_t)b * C8_ + c) * N_ + kt2 + kc * 2);
            }
#pragma unroll
            for (int i = 0; i < 8; i++) {
                int idx = i * 256 + tid;
                int c2 = idx >> 4, kq = idx & 15;
                pre_g[i] = *(const uint2*)(
                    d_g + ((size_t)b * C2_ + c2) * N_ + kt2 + kq * 4);
            }
        }

        float s[8][4];
#pragma unroll
        for (int nt = 0; nt < 8; nt++)
#pragma unroll
            for (int j = 0; j < 4; j++) s[nt][j] = 0.f;

#pragma unroll
        for (int ks = 0; ks < 2; ks++) {
#pragma unroll
            for (int nt = 0; nt < 8; nt++) {
                const __half* pb = phi_s + (nt * 8 + qr) * PHI_STR + ks * 16 + 2 * qc;
                unsigned b0 = *(const unsigned*)pb;
                unsigned b1 = *(const unsigned*)(pb + 8);
                mma_f16(s[nt][0], s[nt][1], s[nt][2], s[nt][3],
                        at[ks][0], at[ks][1], at[ks][2], at[ks][3], b0, b1);
            }
        }

        float rm0 = -1e30f, rm1 = -1e30f;
#pragma unroll
        for (int nt = 0; nt < 8; nt++) {
            rm0 = fmaxf(rm0, fmaxf(s[nt][0], s[nt][1]));
            rm1 = fmaxf(rm1, fmaxf(s[nt][2], s[nt][3]));
        }
        rm0 = fmaxf(rm0, __shfl_xor_sync(0xffffffffu, rm0, 1, 4));
        rm0 = fmaxf(rm0, __shfl_xor_sync(0xffffffffu, rm0, 2, 4));
        rm1 = fmaxf(rm1, __shfl_xor_sync(0xffffffffu, rm1, 1, 4));
        rm1 = fmaxf(rm1, __shfl_xor_sync(0xffffffffu, rm1, 2, 4));
        float mn0 = fmaxf(m0, rm0), mn1 = fmaxf(m1, rm1);
        float cr0 = ex2f(m0 - mn0), cr1 = ex2f(m1 - mn1);
        m0 = mn0; m1 = mn1;
#pragma unroll
        for (int nt = 0; nt < 16; nt++) {
            O[nt][0] *= cr0; O[nt][1] *= cr0;
            O[nt][2] *= cr1; O[nt][3] *= cr1;
        }

        unsigned pk[8][2];
        float rs0 = 0.f, rs1 = 0.f;
#pragma unroll
        for (int nt = 0; nt < 8; nt++) {
            float e0 = ex2f(s[nt][0] - mn0);
            float e1 = ex2f(s[nt][1] - mn0);
            float e2 = ex2f(s[nt][2] - mn1);
            float e3 = ex2f(s[nt][3] - mn1);
            rs0 += e0 + e1; rs1 += e2 + e3;
            pk[nt][0] = packh2(e0, e1);
            pk[nt][1] = packh2(e2, e3);
        }
        l0 = l0 * cr0 + rs0;
        l1 = l1 * cr1 + rs1;

#pragma unroll
        for (int kb = 0; kb < 4; kb++) {
            unsigned a0 = pk[2 * kb][0];
            unsigned a1 = pk[2 * kb][1];
            unsigned a2 = pk[2 * kb + 1][0];
            unsigned a3 = pk[2 * kb + 1][1];
#pragma unroll
            for (int nt = 0; nt < 16; nt++) {
                const __half* gb = g_s + (nt * 8 + qr) * G_STR + kb * 16 + 2 * qc;
                unsigned b0 = *(const unsigned*)gb;
                unsigned b1 = *(const unsigned*)(gb + 8);
                mma_f16(O[nt][0], O[nt][1], O[nt][2], O[nt][3],
                        a0, a1, a2, a3, b0, b1);
            }
        }

        if (has_next) {
#pragma unroll
            for (int i = 0; i < 4; i++) {
                int idx = i * 256 + tid;
                int c = idx >> 5, kc = idx & 31;
                phi_n[(kc * 2) * PHI_STR + c]     = __low2half(pre_phi[i]);
                phi_n[(kc * 2 + 1) * PHI_STR + c] = __high2half(pre_phi[i]);
            }
#pragma unroll
            for (int i = 0; i < 8; i++) {
                int idx = i * 256 + tid;
                int c2 = idx >> 4, kq = idx & 15;
                *(uint2*)(g_n + c2 * G_STR + kq * 4) = pre_g[i];
            }
        }
        __syncthreads();
    }

    l0 += __shfl_xor_sync(0xffffffffu, l0, 1, 4);
    l0 += __shfl_xor_sync(0xffffffffu, l0, 2, 4);
    l1 += __shfl_xor_sync(0xffffffffu, l1, 1, 4);
    l1 += __shfl_xor_sync(0xffffffffu, l1, 2, 4);
    float inv0 = 1.0f / l0;
    float inv1 = 1.0f / l1;

    float* dst0 = d_att + ((size_t)b * N_ + row0) * C2_ + qc * 2;
#pragma unroll
    for (int nt = 0; nt < 16; nt++) {
        *(float2*)(dst0 + nt * 8) =
            make_float2(O[nt][0] * inv0, O[nt][1] * inv0);
        *(float2*)(dst0 + 8 * C2_ + nt * 8) =
            make_float2(O[nt][2] * inv1, O[nt][3] * inv1);
    }
}

// ============================================================================
// Kernel 3: out = w_o @ att + b_o + x via fp16 mma, split-att.
// 128 channels per CTA (4 merged M-groups). Grid.x = 2 * 32 = 64.
// ============================================================================
#define WO_STR 136
#define AT_STR 40

__global__ void __launch_bounds__(256) out_tc_kernel(
    const float* __restrict__ wo, const float* __restrict__ bo,
    const float* __restrict__ x, float* __restrict__ out) {
    extern __shared__ __half smh[];
    __half* w_s = smh;                        // [128][WO_STR]
    __half* ah  = smh + 128 * WO_STR;         // [128][AT_STR]
    __half* al  = ah + 128 * AT_STR;          // [128][AT_STR]

    const int b  = blockIdx.y;
    const int Cbase = (blockIdx.x >> 5) * 128;
    const int N0    = (blockIdx.x & 31) * 128;
    const int tid  = threadIdx.x;
    const int wid  = tid >> 5, lane = tid & 31;
    const int m0   = (wid >> 2) * 16;
    const int n0w  = (wid & 3) * 32;
    const int qr = lane >> 2, qc = lane & 3;

    // stage wo [128 c][128 c2] fp16 once
#pragma unroll
    for (int i = 0; i < 64; i++) {
        int idx = i * 256 + tid;
        int r = idx >> 7, kk = idx & 127;
        w_s[r * WO_STR + kk] = __float2half_rn(wo[(Cbase + r) * C2_ + kk]);
    }

    float acc[4][4][4];
#pragma unroll
    for (int mt = 0; mt < 4; mt++)
#pragma unroll
        for (int nt = 0; nt < 4; nt++)
#pragma unroll
            for (int j = 0; j < 4; j++) acc[mt][nt][j] = 0.f;

    for (int kp = 0; kp < 4; kp++) {
        const int k0 = kp * 32;
        __syncthreads();
        // stage att [128 n][32 k] hi/lo fp16
#pragma unroll
        for (int i = 0; i < 4; i++) {
            int idx = i * 256 + tid;
            int nn = idx >> 3, kk4 = idx & 7;
            float4 v = *(const float4*)(
                d_att + ((size_t)b * N_ + N0 + nn) * C2_ + k0 + kk4 * 4);
            __half2 h01 = __floats2half2_rn(v.x, v.y);
            __half2 h23 = __floats2half2_rn(v.z, v.w);
            __half2 l01 = __floats2half2_rn(v.x - __half2float(__low2half(h01)),
                                            v.y - __half2float(__high2half(h01)));
            __half2 l23 = __floats2half2_rn(v.z - __half2float(__low2half(h23)),
                                            v.w - __half2float(__high2half(h23)));
            *(__half2*)(ah + nn * AT_STR + kk4 * 4)     = h01;
            *(__half2*)(ah + nn * AT_STR + kk4 * 4 + 2) = h23;
            *(__half2*)(al + nn * AT_STR + kk4 * 4)     = l01;
            *(__half2*)(al + nn * AT_STR + kk4 * 4 + 2) = l23;
        }
        __syncthreads();

#pragma unroll
        for (int ks = 0; ks < 2; ks++) {
            // B fragments once, reused across 4 m-tiles
            unsigned bh0[4], bh1[4], bl0[4], bl1[4];
#pragma unroll
            for (int nt = 0; nt < 4; nt++) {
                const __half* bh = ah + (n0w + nt * 8 + qr) * AT_STR + ks * 16 + 2 * qc;
                const __half* bl = al + (n0w + nt * 8 + qr) * AT_STR + ks * 16 + 2 * qc;
                bh0[nt] = *(const unsigned*)bh;
                bh1[nt] = *(const unsigned*)(bh + 8);
                bl0[nt] = *(const unsigned*)bl;
                bl1[nt] = *(const unsigned*)(bl + 8);
            }
#pragma unroll
            for (int mt = 0; mt < 4; mt++) {
                const __half* wrow =
                    w_s + (mt * 32 + m0 + qr) * WO_STR + k0 + ks * 16 + 2 * qc;
                unsigned a0 = *(const unsigned*)wrow;
                unsigned a1 = *(const unsigned*)(wrow + 8 * WO_STR);
                unsigned a2 = *(const unsigned*)(wrow + 8);
                unsigned a3 = *(const unsigned*)(wrow + 8 * WO_STR + 8);
#pragma unroll
                for (int nt = 0; nt < 4; nt++) {
                    mma_f16(acc[mt][nt][0], acc[mt][nt][1],
                            acc[mt][nt][2], acc[mt][nt][3],
                            a0, a1, a2, a3, bh0[nt], bh1[nt]);
                    mma_f16(acc[mt][nt][0], acc[mt][nt][1],
                            acc[mt][nt][2], acc[mt][nt][3],
                            a0, a1, a2, a3, bl0[nt], bl1[nt]);
                }
            }
        }
    }

#pragma unroll
    for (int mt = 0; mt < 4; mt++) {
#pragma unroll
        for (int rr = 0; rr < 2; rr++) {
            int c = Cbase + mt * 32 + m0 + qr + rr * 8;
            float bias = bo[c];
#pragma unroll
            for (int nt = 0; nt < 4; nt++) {
                int n = N0 + n0w + qc * 2 + nt * 8;
                size_t idx = ((size_t)b * C_ + c) * N_ + n;
                float2 xv = *(const float2*)(x + idx);
                *(float2*)(out + idx) = make_float2(
                    acc[mt][nt][rr * 2] + bias + xv.x,
                    acc[mt][nt][rr * 2 + 1] + bias + xv.y);
            }
        }
    }
}

// ============================================================================
extern "C" void kernel_launch(void* const* d_in, const int* in_sizes, int n_in,
                              void* d_out, int out_size) {
    (void)in_sizes; (void)n_in; (void)out_size;
    const float* x  = (const float*)d_in[0];
    const float* wt = (const float*)d_in[1];
    const float* bt = (const float*)d_in[2];
    const float* wp = (const float*)d_in[3];
    const float* bp = (const float*)d_in[4];
    const float* wg = (const float*)d_in[5];
    const float* bg = (const float*)d_in[6];
    const float* wo = (const float*)d_in[7];
    const float* bo = (const float*)d_in[8];
    float* out = (float*)d_out;

    const int smem_proj  = (96 * 36 + 2 * 32 * 136) * 4;          // 48640
    const int smem_flash = 2 * (PHI_BUF + G_BUF) * 2;             // 47104
    const int smem_out   = (128 * WO_STR + 2 * 128 * AT_STR) * 2; // 55296

    cudaFuncSetAttribute(proj_tc_kernel,
                         cudaFuncAttributeMaxDynamicSharedMemorySize, smem_proj);
    cudaFuncSetAttribute(flash_tc_kernel,
                         cudaFuncAttributeMaxDynamicSharedMemorySize, smem_flash);
    cudaFuncSetAttribute(out_tc_kernel,
                         cudaFuncAttributeMaxDynamicSharedMemorySize, smem_out);

    proj_tc_kernel<<<dim3(64, B_), 256, smem_proj>>>(x, wt, bt, wp, bp, wg, bg);
    flash_tc_kernel<<<dim3(N_ / 128, B_), 256, smem_flash>>>();
    out_tc_kernel<<<dim3(64, B_), 256, smem_out>>>(wo, bo, x, out);
}

// round 17
// speedup vs baseline: 1.4272x; 1.0522x over previous
#include <cuda_runtime.h>
#include <cuda_fp16.h>

// NonLocalAttention: B=4, C=256, H=W=64 -> N=4096, C8=32, C2=128
//   proj_tc_kernel : projections (tf32 mma, split-x), 96 outs/CTA (exact R12)
//   flash_tc_kernel: fp16 flash (double-buffered, 128-query CTA, exact R15
//                    mainloop) + FUSED output projection epilogue:
//                    out = w_o @ att + b_o + x  (att never touches gmem)

#define B_ 4
#define C_ 256
#define N_ 4096
#define C8_ 32
#define C2_ 128

__device__ __half d_theta[(size_t)B_ * C8_ * N_];   // theta * log2e
__device__ __half d_phi[(size_t)B_ * C8_ * N_];
__device__ __half d_g[(size_t)B_ * C2_ * N_];       // [b][c2][n]

// ---- intrinsics ----
__device__ __forceinline__ unsigned cvt_tf32(float x) {
    unsigned r;
    asm("cvt.rna.tf32.f32 %0, %1;" : "=r"(r) : "f"(x));
    return r;
}
__device__ __forceinline__ float cvt_tf32f(float x) {
    return __uint_as_float(cvt_tf32(x));
}
__device__ __forceinline__ float ex2f(float x) {
    float r;
    asm("ex2.approx.f32 %0, %1;" : "=f"(r) : "f"(x));
    return r;
}
__device__ __forceinline__ void mma_tf32(
    float& c0, float& c1, float& c2, float& c3,
    unsigned a0, unsigned a1, unsigned a2, unsigned a3,
    unsigned b0, unsigned b1) {
    asm("mma.sync.aligned.m16n8k8.row.col.f32.tf32.tf32.f32 "
        "{%0,%1,%2,%3}, {%4,%5,%6,%7}, {%8,%9}, {%0,%1,%2,%3};"
        : "+f"(c0), "+f"(c1), "+f"(c2), "+f"(c3)
        : "r"(a0), "r"(a1), "r"(a2), "r"(a3), "r"(b0), "r"(b1));
}
__device__ __forceinline__ void mma_f16(
    float& c0, float& c1, float& c2, float& c3,
    unsigned a0, unsigned a1, unsigned a2, unsigned a3,
    unsigned b0, unsigned b1) {
    asm("mma.sync.aligned.m16n8k16.row.col.f32.f16.f16.f32 "
        "{%0,%1,%2,%3}, {%4,%5,%6,%7}, {%8,%9}, {%0,%1,%2,%3};"
        : "+f"(c0), "+f"(c1), "+f"(c2), "+f"(c3)
        : "r"(a0), "r"(a1), "r"(a2), "r"(a3), "r"(b0), "r"(b1));
}
__device__ __forceinline__ unsigned packh2(float lo, float hi) {
    __half2 h = __floats2half2_rn(lo, hi);
    return *(unsigned*)&h;
}

// ============================================================================
// Kernel 1: projections via tf32 mma, split-x. 96 outputs per CTA. (exact R12)
// ============================================================================
__global__ void __launch_bounds__(256) proj_tc_kernel(
    const float* __restrict__ x,
    const float* __restrict__ wt, const float* __restrict__ bt,
    const float* __restrict__ wp, const float* __restrict__ bp,
    const float* __restrict__ wg, const float* __restrict__ bg) {
    extern __shared__ float sm[];
    float* ws = sm;                 // [96][36]
    float* xh = sm + 96 * 36;       // [32][136]
    float* xl = xh + 32 * 136;      // [32][136]

    const int b  = blockIdx.y;
    const int Mbase = (blockIdx.x >> 5) * 96;
    const int N0    = (blockIdx.x & 31) * 128;
    const int tid  = threadIdx.x;
    const int wid  = tid >> 5, lane = tid & 31;
    const int m0   = (wid >> 2) * 16;
    const int n0w  = (wid & 3) * 32;
    const int qr = lane >> 2, qc = lane & 3;

    float acc[3][4][4];
#pragma unroll
    for (int mt = 0; mt < 3; mt++)
#pragma unroll
        for (int nt = 0; nt < 4; nt++)
#pragma unroll
            for (int j = 0; j < 4; j++) acc[mt][nt][j] = 0.f;

    for (int kp = 0; kp < 8; kp++) {
        const int k0 = kp * 32;
        __syncthreads();
#pragma unroll
        for (int i = 0; i < 12; i++) {
            int idx = i * 256 + tid;
            int r = idx >> 5, kk = idx & 31;
            int o = Mbase + r;
            const float* src = (o < 32) ? wt + o * C_
                             : (o < 64) ? wp + (o - 32) * C_
                                        : wg + (o - 64) * C_;
            ws[r * 36 + kk] = cvt_tf32f(src[k0 + kk]);
        }
#pragma unroll
        for (int i = 0; i < 4; i++) {
            int idx = i * 256 + tid;
            int cc = idx >> 5, nn4 = idx & 31;
            float4 v = *(const float4*)(
                x + ((size_t)(b * C_ + k0 + cc)) * N_ + N0 + nn4 * 4);
            float4 h, l;
            h.x = cvt_tf32f(v.x); l.x = v.x - h.x;
            h.y = cvt_tf32f(v.y); l.y = v.y - h.y;
            h.z = cvt_tf32f(v.z); l.z = v.z - h.z;
            h.w = cvt_tf32f(v.w); l.w = v.w - h.w;
            *(float4*)(xh + cc * 136 + nn4 * 4) = h;
            *(float4*)(xl + cc * 136 + nn4 * 4) = l;
        }
        __syncthreads();

#pragma unroll
        for (int ks = 0; ks < 4; ks++) {
            const float* bh = xh + (ks * 8 + qc) * 136 + n0w + qr;
            const float* bl = xl + (ks * 8 + qc) * 136 + n0w + qr;
            unsigned bh0[4], bh1[4], bl0[4], bl1[4];
#pragma unroll
            for (int nt = 0; nt < 4; nt++) {
                bh0[nt] = __float_as_uint(bh[nt * 8]);
                bh1[nt] = __float_as_uint(bh[4 * 136 + nt * 8]);
                bl0[nt] = __float_as_uint(bl[nt * 8]);
                bl1[nt] = __float_as_uint(bl[4 * 136 + nt * 8]);
            }
#pragma unroll
            for (int mt = 0; mt < 3; mt++) {
                const float* wrow = ws + (mt * 32 + m0 + qr) * 36 + ks * 8 + qc;
                unsigned a0 = __float_as_uint(wrow[0]);
                unsigned a1 = __float_as_uint(wrow[8 * 36]);
                unsigned a2 = __float_as_uint(wrow[4]);
                unsigned a3 = __float_as_uint(wrow[8 * 36 + 4]);
#pragma unroll
                for (int nt = 0; nt < 4; nt++) {
                    mma_tf32(acc[mt][nt][0], acc[mt][nt][1],
                             acc[mt][nt][2], acc[mt][nt][3],
                             a0, a1, a2, a3, bh0[nt], bh1[nt]);
                    mma_tf32(acc[mt][nt][0], acc[mt][nt][1],
                             acc[mt][nt][2], acc[mt][nt][3],
                             a0, a1, a2, a3, bl0[nt], bl1[nt]);
                }
            }
        }
    }

    const float LOG2E = 1.4426950408889634f;
#pragma unroll
    for (int mt = 0; mt < 3; mt++) {
#pragma unroll
        for (int rr = 0; rr < 2; rr++) {
            int o = Mbase + mt * 32 + m0 + qr + rr * 8;
            if (o < 32) {
                float bias = bt[o];
                __half2* dst = (__half2*)(d_theta + ((size_t)b * C8_ + o) * N_ +
                                          N0 + n0w + qc * 2);
#pragma unroll
                for (int nt = 0; nt < 4; nt++)
                    dst[nt * 4] = __floats2half2_rn(
                        (acc[mt][nt][rr * 2] + bias) * LOG2E,
                        (acc[mt][nt][rr * 2 + 1] + bias) * LOG2E);
            } else if (o < 64) {
                float bias = bp[o - 32];
                __half2* dst = (__half2*)(d_phi + ((size_t)b * C8_ + (o - 32)) * N_ +
                                          N0 + n0w + qc * 2);
#pragma unroll
                for (int nt = 0; nt < 4; nt++)
                    dst[nt * 4] = __floats2half2_rn(
                        acc[mt][nt][rr * 2] + bias, acc[mt][nt][rr * 2 + 1] + bias);
            } else {
                float bias = bg[o - 64];
                __half2* dst = (__half2*)(d_g + ((size_t)b * C2_ + (o - 64)) * N_ +
                                          N0 + n0w + qc * 2);
#pragma unroll
                for (int nt = 0; nt < 4; nt++)
                    dst[nt * 4] = __floats2half2_rn(
                        acc[mt][nt][rr * 2] + bias, acc[mt][nt][rr * 2 + 1] + bias);
            }
        }
    }
}

// ============================================================================
// Kernel 2: fp16 flash attention + fused output projection epilogue.
// Mainloop identical to R15. Epilogue: O -> smem fp16 h/l, then
// out[256c][128n] = wo @ att + bias + x.
// ============================================================================
#define PHI_STR 40
#define G_STR   72
#define PHI_BUF (64 * PHI_STR)
#define G_BUF   (128 * G_STR)
#define NTILES  (N_ / 64)
#define ATT_STR 136
#define WOE_STR 40
// epilogue smem (halves): att_h[128][136] | att_l[128][136] | wo_s[256][40]
#define EPI_SMEM ((2 * 128 * ATT_STR + 256 * WOE_STR) * 2)
#define FL_SMEM_BYTES (2 * (PHI_BUF + G_BUF) * 2)
#define FUSED_SMEM (EPI_SMEM > FL_SMEM_BYTES ? EPI_SMEM : FL_SMEM_BYTES)

__global__ void __launch_bounds__(256) flash_tc_kernel(
    const float* __restrict__ wo, const float* __restrict__ bo,
    const float* __restrict__ x, float* __restrict__ out) {
    extern __shared__ __half smh[];
    __half* g_base = smh + 2 * PHI_BUF;

    const int b   = blockIdx.y;
    const int q0  = blockIdx.x * 128;
    const int tid = threadIdx.x;
    const int w    = tid >> 5;
    const int lane = tid & 31;
    const int qr = lane >> 2;
    const int qc = lane & 3;
    const int row0 = q0 + w * 16 + qr;

    unsigned at[2][4];
    {
        const __half* tp = d_theta + (size_t)b * C8_ * N_;
#pragma unroll
        for (int ks = 0; ks < 2; ks++) {
            int c = ks * 16 + 2 * qc;
            at[ks][0] = packh2(__half2float(tp[(size_t)c * N_ + row0]),
                               __half2float(tp[(size_t)(c + 1) * N_ + row0]));
            at[ks][1] = packh2(__half2float(tp[(size_t)c * N_ + row0 + 8]),
                               __half2float(tp[(size_t)(c + 1) * N_ + row0 + 8]));
            at[ks][2] = packh2(__half2float(tp[(size_t)(c + 8) * N_ + row0]),
                               __half2float(tp[(size_t)(c + 9) * N_ + row0]));
            at[ks][3] = packh2(__half2float(tp[(size_t)(c + 8) * N_ + row0 + 8]),
                               __half2float(tp[(size_t)(c + 9) * N_ + row0 + 8]));
        }
    }

    float O[16][4];
#pragma unroll
    for (int nt = 0; nt < 16; nt++)
#pragma unroll
        for (int j = 0; j < 4; j++) O[nt][j] = 0.f;
    float m0 = -1e30f, m1 = -1e30f, l0 = 0.f, l1 = 0.f;

    {
        __half* phi_s = smh;
        __half* g_s   = g_base;
#pragma unroll
        for (int i = 0; i < 4; i++) {
            int idx = i * 256 + tid;
            int c = idx >> 5, kc = idx & 31;
            __half2 v = *(const __half2*)(
                d_phi + ((size_t)b * C8_ + c) * N_ + kc * 2);
            phi_s[(kc * 2) * PHI_STR + c]     = __low2half(v);
            phi_s[(kc * 2 + 1) * PHI_STR + c] = __high2half(v);
        }
#pragma unroll
        for (int i = 0; i < 8; i++) {
            int idx = i * 256 + tid;
            int c2 = idx >> 4, kq = idx & 15;
            uint2 v = *(const uint2*)(
                d_g + ((size_t)b * C2_ + c2) * N_ + kq * 4);
            *(uint2*)(g_s + c2 * G_STR + kq * 4) = v;
        }
    }
    __syncthreads();

    for (int it = 0; it < NTILES; it++) {
        const int cur = it & 1;
        __half* phi_s = smh + cur * PHI_BUF;
        __half* g_s   = g_base + cur * G_BUF;
        __half* phi_n = smh + (1 - cur) * PHI_BUF;
        __half* g_n   = g_base + (1 - cur) * G_BUF;

        __half2 pre_phi[4];
        uint2   pre_g[8];
        const bool has_next = (it < NTILES - 1);
        if (has_next) {
            const int kt2 = (it + 1) * 64;
#pragma unroll
            for (int i = 0; i < 4; i++) {
                int idx = i * 256 + tid;
                int c = idx >> 5, kc = idx & 31;
                pre_phi[i] = *(const __half2*)(
                    d_phi + ((size_t)b * C8_ + c) * N_ + kt2 + kc * 2);
            }
#pragma unroll
            for (int i = 0; i < 8; i++) {
                int idx = i * 256 + tid;
                int c2 = idx >> 4, kq = idx & 15;
                pre_g[i] = *(const uint2*)(
                    d_g + ((size_t)b * C2_ + c2) * N_ + kt2 + kq * 4);
            }
        }

        float s[8][4];
#pragma unroll
        for (int nt = 0; nt < 8; nt++)
#pragma unroll
            for (int j = 0; j < 4; j++) s[nt][j] = 0.f;

#pragma unroll
        for (int ks = 0; ks < 2; ks++) {
#pragma unroll
            for (int nt = 0; nt < 8; nt++) {
                const __half* pb = phi_s + (nt * 8 + qr) * PHI_STR + ks * 16 + 2 * qc;
                unsigned b0 = *(const unsigned*)pb;
                unsigned b1 = *(const unsigned*)(pb + 8);
                mma_f16(s[nt][0], s[nt][1], s[nt][2], s[nt][3],
                        at[ks][0], at[ks][1], at[ks][2], at[ks][3], b0, b1);
            }
        }

        float rm0 = -1e30f, rm1 = -1e30f;
#pragma unroll
        for (int nt = 0; nt < 8; nt++) {
            rm0 = fmaxf(rm0, fmaxf(s[nt][0], s[nt][1]));
            rm1 = fmaxf(rm1, fmaxf(s[nt][2], s[nt][3]));
        }
        rm0 = fmaxf(rm0, __shfl_xor_sync(0xffffffffu, rm0, 1, 4));
        rm0 = fmaxf(rm0, __shfl_xor_sync(0xffffffffu, rm0, 2, 4));
        rm1 = fmaxf(rm1, __shfl_xor_sync(0xffffffffu, rm1, 1, 4));
        rm1 = fmaxf(rm1, __shfl_xor_sync(0xffffffffu, rm1, 2, 4));
        float mn0 = fmaxf(m0, rm0), mn1 = fmaxf(m1, rm1);
        float cr0 = ex2f(m0 - mn0), cr1 = ex2f(m1 - mn1);
        m0 = mn0; m1 = mn1;
#pragma unroll
        for (int nt = 0; nt < 16; nt++) {
            O[nt][0] *= cr0; O[nt][1] *= cr0;
            O[nt][2] *= cr1; O[nt][3] *= cr1;
        }

        unsigned pk[8][2];
        float rs0 = 0.f, rs1 = 0.f;
#pragma unroll
        for (int nt = 0; nt < 8; nt++) {
            float e0 = ex2f(s[nt][0] - mn0);
            float e1 = ex2f(s[nt][1] - mn0);
            float e2 = ex2f(s[nt][2] - mn1);
            float e3 = ex2f(s[nt][3] - mn1);
            rs0 += e0 + e1; rs1 += e2 + e3;
            pk[nt][0] = packh2(e0, e1);
            pk[nt][1] = packh2(e2, e3);
        }
        l0 = l0 * cr0 + rs0;
        l1 = l1 * cr1 + rs1;

#pragma unroll
        for (int kb = 0; kb < 4; kb++) {
            unsigned a0 = pk[2 * kb][0];
            unsigned a1 = pk[2 * kb][1];
            unsigned a2 = pk[2 * kb + 1][0];
            unsigned a3 = pk[2 * kb + 1][1];
#pragma unroll
            for (int nt = 0; nt < 16; nt++) {
                const __half* gb = g_s + (nt * 8 + qr) * G_STR + kb * 16 + 2 * qc;
                unsigned b0 = *(const unsigned*)gb;
                unsigned b1 = *(const unsigned*)(gb + 8);
                mma_f16(O[nt][0], O[nt][1], O[nt][2], O[nt][3],
                        a0, a1, a2, a3, b0, b1);
            }
        }

        if (has_next) {
#pragma unroll
            for (int i = 0; i < 4; i++) {
                int idx = i * 256 + tid;
                int c = idx >> 5, kc = idx & 31;
                phi_n[(kc * 2) * PHI_STR + c]     = __low2half(pre_phi[i]);
                phi_n[(kc * 2 + 1) * PHI_STR + c] = __high2half(pre_phi[i]);
            }
#pragma unroll
            for (int i = 0; i < 8; i++) {
                int idx = i * 256 + tid;
                int c2 = idx >> 4, kq = idx & 15;
                *(uint2*)(g_n + c2 * G_STR + kq * 4) = pre_g[i];
            }
        }
        __syncthreads();
    }

    // ---- finalize softmax normalizers ----
    l0 += __shfl_xor_sync(0xffffffffu, l0, 1, 4);
    l0 += __shfl_xor_sync(0xffffffffu, l0, 2, 4);
    l1 += __shfl_xor_sync(0xffffffffu, l1, 1, 4);
    l1 += __shfl_xor_sync(0xffffffffu, l1, 2, 4);
    float inv0 = 1.0f / l0;
    float inv1 = 1.0f / l1;

    // ================= fused output-projection epilogue =================
    __half* att_h = smh;                          // [128][ATT_STR]
    __half* att_l = smh + 128 * ATT_STR;          // [128][ATT_STR]
    __half* wo_s  = smh + 2 * 128 * ATT_STR;      // [256][WOE_STR]

    // store normalized att tile as fp16 h/l (rows = local n, cols = c2)
    {
        const int nl = w * 16 + qr;
#pragma unroll
        for (int nt = 0; nt < 16; nt++) {
            float v0 = O[nt][0] * inv0, v1 = O[nt][1] * inv0;
            float v2 = O[nt][2] * inv1, v3 = O[nt][3] * inv1;
            __half2 h01 = __floats2half2_rn(v0, v1);
            __half2 l01 = __floats2half2_rn(v0 - __half2float(__low2half(h01)),
                                            v1 - __half2float(__high2half(h01)));
            __half2 h23 = __floats2half2_rn(v2, v3);
            __half2 l23 = __floats2half2_rn(v2 - __half2float(__low2half(h23)),
                                            v3 - __half2float(__high2half(h23)));
            *(__half2*)(att_h + nl * ATT_STR + nt * 8 + 2 * qc)        = h01;
            *(__half2*)(att_l + nl * ATT_STR + nt * 8 + 2 * qc)        = l01;
            *(__half2*)(att_h + (nl + 8) * ATT_STR + nt * 8 + 2 * qc)  = h23;
            *(__half2*)(att_l + (nl + 8) * ATT_STR + nt * 8 + 2 * qc)  = l23;
        }
    }
    __syncthreads();

    // GEMM: out[256c][128n] = wo @ att ; warp w owns 32 channels.
    const int m0e = w * 32;
    float acc[2][16][4];
#pragma unroll
    for (int mt = 0; mt < 2; mt++)
#pragma unroll
        for (int nt = 0; nt < 16; nt++)
#pragma unroll
            for (int j = 0; j < 4; j++) acc[mt][nt][j] = 0.f;

    for (int kp = 0; kp < 4; kp++) {
        const int k0 = kp * 32;
        __syncthreads();    // protect wo_s reuse across phases
        // stage wo [256][32] fp16
#pragma unroll
        for (int i = 0; i < 32; i++) {
            int idx = i * 256 + tid;
            int r = idx >> 5, kk = idx & 31;
            wo_s[r * WOE_STR + kk] = __float2half_rn(wo[r * C2_ + k0 + kk]);
        }
        __syncthreads();

#pragma unroll
        for (int ks = 0; ks < 2; ks++) {
            unsigned a[2][4];
#pragma unroll
            for (int mt = 0; mt < 2; mt++) {
                const __half* wrow =
                    wo_s + (m0e + mt * 16 + qr) * WOE_STR + ks * 16 + 2 * qc;
                a[mt][0] = *(const unsigned*)wrow;
                a[mt][1] = *(const unsigned*)(wrow + 8 * WOE_STR);
                a[mt][2] = *(const unsigned*)(wrow + 8);
                a[mt][3] = *(const unsigned*)(wrow + 8 * WOE_STR + 8);
            }
#pragma unroll
            for (int nt = 0; nt < 16; nt++) {
                const __half* bh =
                    att_h + (nt * 8 + qr) * ATT_STR + k0 + ks * 16 + 2 * qc;
                const __half* bl =
                    att_l + (nt * 8 + qr) * ATT_STR + k0 + ks * 16 + 2 * qc;
                unsigned b0 = *(const unsigned*)bh;
                unsigned b1 = *(const unsigned*)(bh + 8);
                unsigned c0 = *(const unsigned*)bl;
                unsigned c1 = *(const unsigned*)(bl + 8);
#pragma unroll
                for (int mt = 0; mt < 2; mt++) {
                    mma_f16(acc[mt][nt][0], acc[mt][nt][1],
                            acc[mt][nt][2], acc[mt][nt][3],
                            a[mt][0], a[mt][1], a[mt][2], a[mt][3], b0, b1);
                    mma_f16(acc[mt][nt][0], acc[mt][nt][1],
                            acc[mt][nt][2], acc[mt][nt][3],
                            a[mt][0], a[mt][1], a[mt][2], a[mt][3], c0, c1);
                }
            }
        }
    }

    // bias + residual + store
#pragma unroll
    for (int mt = 0; mt < 2; mt++) {
#pragma unroll
        for (int rr = 0; rr < 2; rr++) {
            int c = m0e + mt * 16 + qr + rr * 8;
            float bias = bo[c];
#pragma unroll
            for (int nt = 0; nt < 16; nt++) {
                int n = q0 + nt * 8 + qc * 2;
                size_t idx = ((size_t)b * C_ + c) * N_ + n;
                float2 xv = *(const float2*)(x + idx);
                *(float2*)(out + idx) = make_float2(
                    acc[mt][nt][rr * 2] + bias + xv.x,
                    acc[mt][nt][rr * 2 + 1] + bias + xv.y);
            }
        }
    }
}

// ============================================================================
extern "C" void kernel_launch(void* const* d_in, const int* in_sizes, int n_in,
                              void* d_out, int out_size) {
    (void)in_sizes; (void)n_in; (void)out_size;
    const float* x  = (const float*)d_in[0];
    const float* wt = (const float*)d_in[1];
    const float* bt = (const float*)d_in[2];
    const float* wp = (const float*)d_in[3];
    const float* bp = (const float*)d_in[4];
    const float* wg = (const float*)d_in[5];
    const float* bg = (const float*)d_in[6];
    const float* wo = (const float*)d_in[7];
    const float* bo = (const float*)d_in[8];
    float* out = (float*)d_out;

    const int smem_proj  = (96 * 36 + 2 * 32 * 136) * 4;   // 48640
    const int smem_flash = FUSED_SMEM;                      // 90112

    cudaFuncSetAttribute(proj_tc_kernel,
                         cudaFuncAttributeMaxDynamicSharedMemorySize, smem_proj);
    cudaFuncSetAttribute(flash_tc_kernel,
                         cudaFuncAttributeMaxDynamicSharedMemorySize, smem_flash);

    proj_tc_kernel<<<dim3(64, B_), 256, smem_proj>>>(x, wt, bt, wp, bp, wg, bg);
    flash_tc_kernel<<<dim3(N_ / 128, B_), 256, smem_flash>>>(wo, bo, x, out);
}